// round 13
// baseline (speedup 1.0000x reference)
#include <cuda_runtime.h>
#include <cuda_bf16.h>
#include <cuda_fp16.h>
#include <cstdint>
#include <cstddef>

#define B_  2
#define S_  2048
#define DM  1024
#define H_  16
#define DH  64
#define M_  (B_*S_)   // 4096
#define NEGINF -1e30f
#define QSCALE (0.125f * 1.44269504088896f)

#define XSEG (M_*DM)
#define WSEG (DM*DM)
#define QKV  (B_*H_*S_*DH)

__device__ unsigned short g_xh[3*XSEG];                 // X: single fp16
__device__ unsigned short g_wh[3*WSEG];                 // W: single fp16
__device__ unsigned short g_qh[QKV];                    // Q: single fp16 (scaled)
__device__ unsigned short g_kh[QKV];                    // K: single fp16
__device__ unsigned short g_vh[QKV];                    // V: single fp16
// mask bias, FRAGMENT-MAJOR: uint4 chunk index =
//   (((bz*8+qb)*32 + kt)*4 + cpart)*512 + tid   (cpart = r*2 + half)
__device__ unsigned short g_mb[(size_t)B_*S_*S_];
__device__ int g_mask_mode;

// ---------------------------------------------------------------------------
__device__ __forceinline__ uint32_t smem_u32(const void* p) {
    uint32_t a;
    asm("{ .reg .u64 t; cvta.to.shared.u64 t, %1; cvt.u32.u64 %0, t; }"
        : "=r"(a) : "l"(p));
    return a;
}
__device__ __forceinline__ void ldsm4(uint32_t addr, uint32_t* r) {
    asm volatile("ldmatrix.sync.aligned.m8n8.x4.shared.b16 {%0,%1,%2,%3}, [%4];"
        : "=r"(r[0]), "=r"(r[1]), "=r"(r[2]), "=r"(r[3]) : "r"(addr));
}
__device__ __forceinline__ void ldsm4t(uint32_t addr, uint32_t* r) {
    asm volatile("ldmatrix.sync.aligned.m8n8.x4.trans.shared.b16 {%0,%1,%2,%3}, [%4];"
        : "=r"(r[0]), "=r"(r[1]), "=r"(r[2]), "=r"(r[3]) : "r"(addr));
}
__device__ __forceinline__ void mma16816f(float* c, const uint32_t* a,
                                          uint32_t b0, uint32_t b1) {
    asm volatile(
        "mma.sync.aligned.m16n8k16.row.col.f32.f16.f16.f32 "
        "{%0,%1,%2,%3}, {%4,%5,%6,%7}, {%8,%9}, {%0,%1,%2,%3};"
        : "+f"(c[0]), "+f"(c[1]), "+f"(c[2]), "+f"(c[3])
        : "r"(a[0]), "r"(a[1]), "r"(a[2]), "r"(a[3]), "r"(b0), "r"(b1));
}
__device__ __forceinline__ uint32_t cvt2_f16(float lo_elem, float hi_elem) {
    uint32_t r;
    asm("cvt.rn.f16x2.f32 %0, %1, %2;" : "=r"(r) : "f"(hi_elem), "f"(lo_elem));
    return r;
}
__device__ __forceinline__ float bf16lo_f(uint32_t v) { return __uint_as_float(v << 16); }
__device__ __forceinline__ float bf16hi_f(uint32_t v) { return __uint_as_float(v & 0xFFFF0000u); }
__device__ __forceinline__ float ex2f(float x) {
    float y;
    asm("ex2.approx.f32 %0, %1;" : "=f"(y) : "f"(x));
    return y;
}
#define CP16(dst, src) \
    asm volatile("cp.async.cg.shared.global [%0], [%1], 16;" :: "r"(dst), "l"(src))
#define CP_COMMIT() asm volatile("cp.async.commit_group;")
#define CP_WAIT1()  asm volatile("cp.async.wait_group 1;")
#define CP_WAIT0()  asm volatile("cp.async.wait_group 0;")

// ---------------------------------------------------------------------------
// Mask dtype detection (own tiny kernel so mask_conv can fork early).
// ---------------------------------------------------------------------------
__global__ void detect_mask_kernel(const unsigned int* __restrict__ m) {
    int t = threadIdx.x;
    int ok_i32 = 1, ok_u8 = 1;
    for (int i = t; i < 4096; i += 256) {
        unsigned w = m[i];
        ok_i32 &= (w <= 1u);
        ok_u8  &= ((w & 0xFEFEFEFEu) == 0u);
    }
    ok_i32 = __syncthreads_and(ok_i32);
    ok_u8  = __syncthreads_and(ok_u8);
    if (t == 0) g_mask_mode = ok_i32 ? 0 : (ok_u8 ? 1 : 2);
}

// ---------------------------------------------------------------------------
// Convert fp32 -> single fp16 planes (X and W).
// ---------------------------------------------------------------------------
struct ConvArgs { const float* src[6]; };

__global__ __launch_bounds__(256) void convert_kernel(ConvArgs a) {
    const int z = blockIdx.z;
    const int tid = threadIdx.x;
    const float4* src = (const float4*)a.src[z];
    int nf8;
    unsigned short* dh;
    if (z < 3) { nf8 = XSEG / 8; dh = g_xh + (size_t)z * XSEG; }
    else       { nf8 = WSEG / 8; dh = g_wh + (size_t)(z - 3) * WSEG; }
    for (int i = blockIdx.x * 256 + tid; i < nf8; i += 1024 * 256) {
        float4 v0 = src[2 * i];
        float4 v1 = src[2 * i + 1];
        uint4 hv;
        hv.x = cvt2_f16(v0.x, v0.y);
        hv.y = cvt2_f16(v0.z, v0.w);
        hv.z = cvt2_f16(v1.x, v1.y);
        hv.w = cvt2_f16(v1.z, v1.w);
        ((uint4*)dh)[i] = hv;
    }
}

// ---------------------------------------------------------------------------
// Mask -> bf16 additive bias in FRAGMENT-MAJOR layout.
// One thread per 16B output chunk (8 bf16).
// chunk ch: tid_part = ch&511, cpart = (ch>>9)&3, kt = (ch>>11)&31,
//           qb = (ch>>16)&7, bz = ch>>19.
// row = qb*256 + 16*(tid_part>>5) + ((tid_part&31)>>2) + 8*(cpart>>1)
// cols = kt*64 + (cpart&1)*32 + j*8 + 2*(tid_part&3) + c,  j=0..3, c=0..1
// ---------------------------------------------------------------------------
__global__ __launch_bounds__(256) void mask_conv_kernel(const void* mask) {
    const int mode = g_mask_mode;
    __nv_bfloat16 nb = __float2bfloat16(NEGINF);
    const uint32_t neg = (uint32_t)*(unsigned short*)&nb;
    const int ch = blockIdx.x * 256 + threadIdx.x;   // grid exactly covers

    const int tp    = ch & 511;
    const int cpart = (ch >> 9) & 3;
    const int kt    = (ch >> 11) & 31;
    const int qb    = (ch >> 16) & 7;
    const int bz    = ch >> 19;

    const int lane = tp & 31;
    const int row  = qb * 256 + 16 * (tp >> 5) + (lane >> 2) + 8 * (cpart >> 1);
    const int col0 = kt * 64 + (cpart & 1) * 32 + 2 * (lane & 3);
    const size_t base = ((size_t)bz * S_ + row) * S_ + col0;

    unsigned m[8];
    if (mode == 0) {
        const int* mp = (const int*)mask;
#pragma unroll
        for (int j = 0; j < 4; ++j) {
            int2 v = *(const int2*)(mp + base + j * 8);
            m[2 * j]     = v.x != 0;
            m[2 * j + 1] = v.y != 0;
        }
    } else if (mode == 1) {
        const unsigned char* mp = (const unsigned char*)mask;
#pragma unroll
        for (int j = 0; j < 4; ++j) {
            unsigned short v = *(const unsigned short*)(mp + base + j * 8);
            m[2 * j]     = v & 0x00FF;
            m[2 * j + 1] = v & 0xFF00;
        }
    } else {
        const float* mp = (const float*)mask;
#pragma unroll
        for (int j = 0; j < 4; ++j) {
            float2 v = *(const float2*)(mp + base + j * 8);
            m[2 * j]     = v.x != 0.f;
            m[2 * j + 1] = v.y != 0.f;
        }
    }
    uint4 o;
    o.x = (m[0] ? neg : 0u) | ((m[1] ? neg : 0u) << 16);
    o.y = (m[2] ? neg : 0u) | ((m[3] ? neg : 0u) << 16);
    o.z = (m[4] ? neg : 0u) | ((m[5] ? neg : 0u) << 16);
    o.w = (m[6] ? neg : 0u) | ((m[7] ? neg : 0u) << 16);
    ((uint4*)g_mb)[ch] = o;
}

// ---------------------------------------------------------------------------
// Projection GEMM: fp16 x fp16, fp32 accumulate.
// BM=BN=128, BK=32, 256 threads (8 warps: 4m x 2n, warp tile 32x64),
// 3-stage cp.async (16KB/stage). 3 CTAs/SM.
// ---------------------------------------------------------------------------
#define PSTG 16384u
#define PROJ_SMEM (3u * PSTG)   // 49152

struct ProjArgs { const float* bias[3]; float scale[3]; };

__device__ __forceinline__ void proj_issue(
    uint32_t sb, int st, int kt, int tid, int m0, int n0,
    const unsigned short* Xh, const unsigned short* Wh)
{
    const uint32_t stage = sb + (uint32_t)st * PSTG;
#pragma unroll
    for (int j = 0; j < 2; ++j) {   // X: 512 lines
        int line = tid + 256 * j;
        int row = line >> 2, c = line & 3;
        uint32_t doff = (uint32_t)row * 64u + (uint32_t)((c ^ ((row >> 1) & 3)) << 4);
        CP16(stage + doff, Xh + (size_t)(m0 + row) * DM + kt * 32 + c * 8);
    }
#pragma unroll
    for (int j = 0; j < 2; ++j) {   // W: 512 lines
        int line = tid + 256 * j;
        int row = line >> 2, c = line & 3;
        uint32_t doff = (uint32_t)row * 64u + (uint32_t)((c ^ ((row >> 1) & 3)) << 4);
        CP16(stage + 8192u + doff, Wh + (size_t)(n0 + row) * DM + kt * 32 + c * 8);
    }
    CP_COMMIT();
}

__global__ __launch_bounds__(256, 3) void proj_mma_kernel(ProjArgs args) {
    extern __shared__ char ps[];
    const uint32_t sb = smem_u32(ps);
    const int z = blockIdx.z;
    const unsigned short* __restrict__ Xh = g_xh + (size_t)z * XSEG;
    const unsigned short* __restrict__ Wh = g_wh + (size_t)z * WSEG;
    const float* __restrict__ bias = args.bias[z];
    const float scale = args.scale[z];
    unsigned short* __restrict__ dst = (z == 0) ? g_qh : (z == 1) ? g_kh : g_vh;

    const int tid = threadIdx.x, lane = tid & 31, wid = tid >> 5;
    const int wm = wid & 3, wn = wid >> 2;          // 32m x 64n warp tiles
    const int m0 = blockIdx.y * 128, n0 = blockIdx.x * 128;
    const int flr = lane & 15, flc = lane >> 4;

    float C[2][8][4];
#pragma unroll
    for (int i = 0; i < 2; ++i)
#pragma unroll
        for (int j = 0; j < 8; ++j)
#pragma unroll
            for (int k = 0; k < 4; ++k) C[i][j][k] = 0.f;

    proj_issue(sb, 0, 0, tid, m0, n0, Xh, Wh);
    proj_issue(sb, 1, 1, tid, m0, n0, Xh, Wh);

    for (int kt = 0; kt < 32; ++kt) {
        if (kt < 31) CP_WAIT1(); else CP_WAIT0();
        __syncthreads();
        if (kt + 2 < 32)
            proj_issue(sb, (kt + 2) % 3, kt + 2, tid, m0, n0, Xh, Wh);

        const uint32_t base = sb + (uint32_t)(kt % 3) * PSTG;
#pragma unroll
        for (int ks = 0; ks < 2; ++ks) {
            const uint32_t csw = (uint32_t)(((2 * ks + flc) ^ ((flr >> 1) & 3)) << 4);
            uint32_t a4[2][4];
#pragma unroll
            for (int mt = 0; mt < 2; ++mt) {
                uint32_t off = (uint32_t)((32 * wm + 16 * mt + flr) * 64) + csw;
                ldsm4(base + off, a4[mt]);
            }
#pragma unroll
            for (int ntp = 0; ntp < 4; ++ntp) {
                uint32_t boff = (uint32_t)((64 * wn + 16 * ntp + flr) * 64) + csw;
                uint32_t b4[4];
                ldsm4(base + 8192u + boff, b4);
                mma16816f(C[0][2 * ntp],     a4[0], b4[0], b4[2]);
                mma16816f(C[1][2 * ntp],     a4[1], b4[0], b4[2]);
                mma16816f(C[0][2 * ntp + 1], a4[0], b4[1], b4[3]);
                mma16816f(C[1][2 * ntp + 1], a4[1], b4[1], b4[3]);
            }
        }
    }

    // epilogue: bias + scale -> fp16, head-split
#pragma unroll
    for (int nt = 0; nt < 8; ++nt) {
        int n = n0 + 64 * wn + 8 * nt + 2 * (lane & 3);
        int h = n >> 6, d = n & 63;
        float2 bv = *(const float2*)(bias + n);
#pragma unroll
        for (int mt = 0; mt < 2; ++mt) {
            int mbase = m0 + 32 * wm + 16 * mt + (lane >> 2);
#pragma unroll
            for (int half = 0; half < 2; ++half) {
                int m = mbase + 8 * half;
                int b = m >> 11, s = m & (S_ - 1);
                float vx = (C[mt][nt][2 * half + 0] + bv.x) * scale;
                float vy = (C[mt][nt][2 * half + 1] + bv.y) * scale;
                size_t off = ((size_t)(b * H_ + h) * S_ + s) * DH + d;
                *(uint32_t*)(dst + off) = cvt2_f16(vx, vy);
            }
        }
    }
}

// ---------------------------------------------------------------------------
// Flash attention: fp16, fragment-major mask via 4 coalesced LDG.128/iter.
// 512 threads, 16 warps x 16 q-rows. Stage (16KB): K@0 | V@8K, 3 stages.
// Q plane @49152 (32KB). Total 81920.
// ---------------------------------------------------------------------------
#define ASTG 16384u
#define AQOFF 49152u
#define ATTN_SMEM 81920u

__device__ __forceinline__ void attn_issue_kv(uint32_t sb, int st, int kt,
                                              int tid, size_t bhS) {
#pragma unroll
    for (int j = 0; j < 2; ++j) {
        int cid = tid + 512 * j;
        int sub = cid >> 9, w = cid & 511, row = w >> 3, c = w & 7;
        const unsigned short* plane = sub ? g_vh : g_kh;
        const void* src = plane + (bhS + (size_t)(kt * 64 + row)) * DH + c * 8;
        uint32_t dst = sb + (uint32_t)st * ASTG + (uint32_t)sub * 8192u
                     + (uint32_t)row * 128u + (uint32_t)((c ^ (row & 7)) << 4);
        CP16(dst, src);
    }
    CP_COMMIT();
}

__global__ __launch_bounds__(512) void attn_mma_kernel(float* __restrict__ out)
{
    extern __shared__ char as_[];
    const uint32_t sb = smem_u32(as_);

    const int tid = threadIdx.x, lane = tid & 31, wid = tid >> 5;
    const int bz = blockIdx.z, h = blockIdx.y;
    const int qb = blockIdx.x;
    const int q0 = qb * 256;
    const size_t bhS = (size_t)(bz * H_ + h) * S_;

    const int flr = lane & 15, flc = lane >> 4;
    const int r_in = lane >> 2;
    const int c_in = 2 * (lane & 3);

    // prologue: Q plane + tiles 0,1
    {
#pragma unroll
        for (int j = 0; j < 4; ++j) {
            int cid = tid + 512 * j;
            int row = cid >> 3, c = cid & 7;
            const void* src = g_qh + (bhS + (size_t)(q0 + row)) * DH + c * 8;
            uint32_t dst = sb + AQOFF
                         + (uint32_t)row * 128u + (uint32_t)((c ^ (row & 7)) << 4);
            CP16(dst, src);
        }
    }
    attn_issue_kv(sb, 0, 0, tid, bhS);
    attn_issue_kv(sb, 1, 1, tid, bhS);

    // wait for group 0 (Q + tile0), hoist Q fragments
    CP_WAIT1();
    __syncthreads();
    const int qrow = 16 * wid + flr;
    uint32_t qf[4][4];
#pragma unroll
    for (int ks = 0; ks < 4; ++ks) {
        uint32_t qoff = (uint32_t)(qrow * 128)
                      + (uint32_t)(((2 * ks + flc) ^ (qrow & 7)) << 4);
        ldsm4(sb + AQOFF + qoff, qf[ks]);
    }

    float oC[8][4];
#pragma unroll
    for (int j = 0; j < 8; ++j)
#pragma unroll
        for (int k = 0; k < 4; ++k) oC[j][k] = 0.f;
    float mi0 = NEGINF, mi1 = NEGINF, li0 = 0.f, li1 = 0.f;

    const int rowA0 = q0 + 16 * wid + r_in;
    // fragment-major mask base for this (bz, qb): chunks of 16B
    const uint4* mb4 = (const uint4*)g_mb
                     + ((size_t)(bz * 8 + qb) * 32) * 4 * 512 + tid;

    for (int kt = 0; kt < 32; ++kt) {
        if (kt < 31) CP_WAIT1(); else CP_WAIT0();
        __syncthreads();
        if (kt + 2 < 32) attn_issue_kv(sb, (kt + 2) % 3, kt + 2, tid, bhS);

        const uint32_t base = sb + (uint32_t)(kt % 3) * ASTG;

        // S init from fragment-major mask bias: 4 coalesced LDG.128
        const uint4* mi_ = mb4 + (size_t)kt * 4 * 512;
        uint4 c0 = mi_[0];          // r=0, half=0 -> sC[0..3][0,1]
        uint4 c1 = mi_[512];        // r=0, half=1 -> sC[4..7][0,1]
        uint4 c2 = mi_[1024];       // r=1, half=0 -> sC[0..3][2,3]
        uint4 c3 = mi_[1536];       // r=1, half=1 -> sC[4..7][2,3]
        float sC[8][4];
        {
            uint32_t a0[4] = {c0.x, c0.y, c0.z, c0.w};
            uint32_t a1[4] = {c1.x, c1.y, c1.z, c1.w};
            uint32_t a2[4] = {c2.x, c2.y, c2.z, c2.w};
            uint32_t a3[4] = {c3.x, c3.y, c3.z, c3.w};
#pragma unroll
            for (int j = 0; j < 4; ++j) {
                sC[j][0]     = bf16lo_f(a0[j]); sC[j][1]     = bf16hi_f(a0[j]);
                sC[4 + j][0] = bf16lo_f(a1[j]); sC[4 + j][1] = bf16hi_f(a1[j]);
                sC[j][2]     = bf16lo_f(a2[j]); sC[j][3]     = bf16hi_f(a2[j]);
                sC[4 + j][2] = bf16lo_f(a3[j]); sC[4 + j][3] = bf16hi_f(a3[j]);
            }
        }

        // -- S += Q K^T --
#pragma unroll
        for (int ks = 0; ks < 4; ++ks) {
            uint32_t k4[4][4];
#pragma unroll
            for (int ntp = 0; ntp < 4; ++ntp) {
                uint32_t koff = (uint32_t)((16 * ntp + flr) * 128)
                              + (uint32_t)(((2 * ks + flc) ^ (flr & 7)) << 4);
                ldsm4(base + koff, k4[ntp]);
            }
#pragma unroll
            for (int ntp = 0; ntp < 4; ++ntp) {
                mma16816f(sC[2 * ntp],     qf[ks], k4[ntp][0], k4[ntp][2]);
                mma16816f(sC[2 * ntp + 1], qf[ks], k4[ntp][1], k4[ntp][3]);
            }
        }

        // -- online softmax (log2 domain) --
        float mx0 = NEGINF, mx1 = NEGINF;
#pragma unroll
        for (int nt = 0; nt < 8; ++nt) {
            mx0 = fmaxf(mx0, fmaxf(sC[nt][0], sC[nt][1]));
            mx1 = fmaxf(mx1, fmaxf(sC[nt][2], sC[nt][3]));
        }
        mx0 = fmaxf(mx0, __shfl_xor_sync(0xffffffffu, mx0, 1));
        mx0 = fmaxf(mx0, __shfl_xor_sync(0xffffffffu, mx0, 2));
        mx1 = fmaxf(mx1, __shfl_xor_sync(0xffffffffu, mx1, 1));
        mx1 = fmaxf(mx1, __shfl_xor_sync(0xffffffffu, mx1, 2));

        float mn0 = fmaxf(mi0, mx0), mn1 = fmaxf(mi1, mx1);
        float f0 = ex2f(mi0 - mn0), f1 = ex2f(mi1 - mn1);
        float sum0 = 0.f, sum1 = 0.f;
#pragma unroll
        for (int nt = 0; nt < 8; ++nt) {
            sC[nt][0] = ex2f(sC[nt][0] - mn0);
            sC[nt][1] = ex2f(sC[nt][1] - mn0);
            sC[nt][2] = ex2f(sC[nt][2] - mn1);
            sC[nt][3] = ex2f(sC[nt][3] - mn1);
            sum0 += sC[nt][0] + sC[nt][1];
            sum1 += sC[nt][2] + sC[nt][3];
        }
        sum0 += __shfl_xor_sync(0xffffffffu, sum0, 1);
        sum0 += __shfl_xor_sync(0xffffffffu, sum0, 2);
        sum1 += __shfl_xor_sync(0xffffffffu, sum1, 1);
        sum1 += __shfl_xor_sync(0xffffffffu, sum1, 2);
        li0 = li0 * f0 + sum0;
        li1 = li1 * f1 + sum1;
        mi0 = mn0; mi1 = mn1;
#pragma unroll
        for (int nt = 0; nt < 8; ++nt) {
            oC[nt][0] *= f0; oC[nt][1] *= f0;
            oC[nt][2] *= f1; oC[nt][3] *= f1;
        }

        // -- O += P V --
#pragma unroll
        for (int kp = 0; kp < 4; ++kp) {
            uint32_t pa[4];
            pa[0] = cvt2_f16(sC[2 * kp][0],     sC[2 * kp][1]);
            pa[1] = cvt2_f16(sC[2 * kp][2],     sC[2 * kp][3]);
            pa[2] = cvt2_f16(sC[2 * kp + 1][0], sC[2 * kp + 1][1]);
            pa[3] = cvt2_f16(sC[2 * kp + 1][2], sC[2 * kp + 1][3]);

            const int trow = kp * 16 + ((lane >> 3) & 1) * 8 + (lane & 7);
            const int cb = lane >> 4;
            uint32_t v4[4][4];
#pragma unroll
            for (int ntp = 0; ntp < 4; ++ntp) {
                uint32_t voff = (uint32_t)(trow * 128)
                              + (uint32_t)(((2 * ntp + cb) ^ (trow & 7)) << 4);
                ldsm4t(base + 8192u + voff, v4[ntp]);
            }
#pragma unroll
            for (int ntp = 0; ntp < 4; ++ntp) {
                mma16816f(oC[2 * ntp],     pa, v4[ntp][0], v4[ntp][1]);
                mma16816f(oC[2 * ntp + 1], pa, v4[ntp][2], v4[ntp][3]);
            }
        }
    }

    // ---- epilogue ----
    float inv0 = (li0 > 0.f) ? 1.0f / li0 : 0.f;
    float inv1 = (li1 > 0.f) ? 1.0f / li1 : 0.f;
    const int qr = rowA0;
    const int d0 = h * DH + c_in;
#pragma unroll
    for (int nt = 0; nt < 8; ++nt) {
        float2 v0, v1;
        v0.x = oC[nt][0] * inv0; v0.y = oC[nt][1] * inv0;
        v1.x = oC[nt][2] * inv1; v1.y = oC[nt][3] * inv1;
        *(float2*)(out + (size_t)(bz * S_ + qr) * DM + d0 + 8 * nt) = v0;
        *(float2*)(out + (size_t)(bz * S_ + qr + 8) * DM + d0 + 8 * nt) = v1;
    }
}

// ---------------------------------------------------------------------------
extern "C" void kernel_launch(void* const* d_in, const int* in_sizes, int n_in,
                              void* d_out, int out_size) {
    const void* mask = d_in[3];
    float* out = (float*)d_out;

    static int init_done = 0;
    static cudaStream_t s2 = 0;
    static cudaEvent_t evA = 0, evB = 0;
    if (!init_done) {
        cudaFuncSetAttribute(proj_mma_kernel,
                             cudaFuncAttributeMaxDynamicSharedMemorySize, PROJ_SMEM);
        cudaFuncSetAttribute(attn_mma_kernel,
                             cudaFuncAttributeMaxDynamicSharedMemorySize, ATTN_SMEM);
        if (cudaStreamCreateWithFlags(&s2, cudaStreamNonBlocking) != cudaSuccess)
            s2 = 0;
        cudaEventCreateWithFlags(&evA, cudaEventDisableTiming);
        cudaEventCreateWithFlags(&evB, cudaEventDisableTiming);
        init_done = 1;
    }

    // 1) mask dtype detection on main stream
    detect_mask_kernel<<<1, 256>>>((const unsigned int*)mask);

    // 2) fork: mask_conv on s2 (overlaps convert + proj)
    cudaStream_t ms = s2 ? s2 : (cudaStream_t)0;
    if (s2) {
        cudaEventRecord(evA, 0);
        cudaStreamWaitEvent(s2, evA, 0);
    }
    mask_conv_kernel<<<4096, 256, 0, ms>>>(mask);
    if (s2) cudaEventRecord(evB, s2);

    // 3) convert + projections on main stream
    ConvArgs ca;
    ca.src[0] = (const float*)d_in[0];
    ca.src[1] = (const float*)d_in[1];
    ca.src[2] = (const float*)d_in[2];
    ca.src[3] = (const float*)d_in[4];
    ca.src[4] = (const float*)d_in[6];
    ca.src[5] = (const float*)d_in[8];
    convert_kernel<<<dim3(1024, 1, 6), 256>>>(ca);

    ProjArgs pa;
    pa.bias[0] = (const float*)d_in[5];
    pa.bias[1] = (const float*)d_in[7];
    pa.bias[2] = (const float*)d_in[9];
    pa.scale[0] = QSCALE; pa.scale[1] = 1.0f; pa.scale[2] = 1.0f;
    proj_mma_kernel<<<dim3(8, 32, 3), 256, PROJ_SMEM>>>(pa);

    // 4) join, then attention
    if (s2) cudaStreamWaitEvent(0, evB, 0);
    attn_mma_kernel<<<dim3(8, 16, 2), 512, ATTN_SMEM>>>(out);
}

// round 14
// speedup vs baseline: 1.2862x; 1.2862x over previous
#include <cuda_runtime.h>
#include <cuda_bf16.h>
#include <cuda_fp16.h>
#include <cstdint>
#include <cstddef>

#define B_  2
#define S_  2048
#define DM  1024
#define H_  16
#define DH  64
#define M_  (B_*S_)   // 4096
#define NEGINF -1e30f
#define QSCALE (0.125f * 1.44269504088896f)

#define XSEG (M_*DM)
#define WSEG (DM*DM)
#define QKV  (B_*H_*S_*DH)

__device__ unsigned short g_xh[3*XSEG];                 // X: single fp16
__device__ unsigned short g_wh[3*WSEG];                 // W: single fp16
__device__ unsigned short g_qh[QKV];                    // Q: single fp16 (scaled)
__device__ unsigned short g_kh[QKV];                    // K: single fp16
__device__ unsigned short g_vh[QKV];                    // V: single fp16
// mask bias, FRAGMENT-MAJOR: uint4 chunk index =
//   (((bz*8+qb)*32 + kt)*4 + cpart)*512 + tid
__device__ unsigned short g_mb[(size_t)B_*S_*S_];
__device__ int g_mask_mode;

// ---------------------------------------------------------------------------
__device__ __forceinline__ uint32_t smem_u32(const void* p) {
    uint32_t a;
    asm("{ .reg .u64 t; cvta.to.shared.u64 t, %1; cvt.u32.u64 %0, t; }"
        : "=r"(a) : "l"(p));
    return a;
}
__device__ __forceinline__ void ldsm4(uint32_t addr, uint32_t* r) {
    asm volatile("ldmatrix.sync.aligned.m8n8.x4.shared.b16 {%0,%1,%2,%3}, [%4];"
        : "=r"(r[0]), "=r"(r[1]), "=r"(r[2]), "=r"(r[3]) : "r"(addr));
}
__device__ __forceinline__ void ldsm4t(uint32_t addr, uint32_t* r) {
    asm volatile("ldmatrix.sync.aligned.m8n8.x4.trans.shared.b16 {%0,%1,%2,%3}, [%4];"
        : "=r"(r[0]), "=r"(r[1]), "=r"(r[2]), "=r"(r[3]) : "r"(addr));
}
__device__ __forceinline__ void mma16816f(float* c, const uint32_t* a,
                                          uint32_t b0, uint32_t b1) {
    asm volatile(
        "mma.sync.aligned.m16n8k16.row.col.f32.f16.f16.f32 "
        "{%0,%1,%2,%3}, {%4,%5,%6,%7}, {%8,%9}, {%0,%1,%2,%3};"
        : "+f"(c[0]), "+f"(c[1]), "+f"(c[2]), "+f"(c[3])
        : "r"(a[0]), "r"(a[1]), "r"(a[2]), "r"(a[3]), "r"(b0), "r"(b1));
}
__device__ __forceinline__ uint32_t cvt2_f16(float lo_elem, float hi_elem) {
    uint32_t r;
    asm("cvt.rn.f16x2.f32 %0, %1, %2;" : "=r"(r) : "f"(hi_elem), "f"(lo_elem));
    return r;
}
__device__ __forceinline__ float bf16lo_f(uint32_t v) { return __uint_as_float(v << 16); }
__device__ __forceinline__ float bf16hi_f(uint32_t v) { return __uint_as_float(v & 0xFFFF0000u); }
__device__ __forceinline__ float ex2f(float x) {
    float y;
    asm("ex2.approx.f32 %0, %1;" : "=f"(y) : "f"(x));
    return y;
}
#define CP16(dst, src) \
    asm volatile("cp.async.cg.shared.global [%0], [%1], 16;" :: "r"(dst), "l"(src))
#define CP_COMMIT() asm volatile("cp.async.commit_group;")
#define CP_WAIT1()  asm volatile("cp.async.wait_group 1;")
#define CP_WAIT0()  asm volatile("cp.async.wait_group 0;")

// ---------------------------------------------------------------------------
// Mask dtype detection.
// ---------------------------------------------------------------------------
__global__ void detect_mask_kernel(const unsigned int* __restrict__ m) {
    int t = threadIdx.x;
    int ok_i32 = 1, ok_u8 = 1;
    for (int i = t; i < 4096; i += 256) {
        unsigned w = m[i];
        ok_i32 &= (w <= 1u);
        ok_u8  &= ((w & 0xFEFEFEFEu) == 0u);
    }
    ok_i32 = __syncthreads_and(ok_i32);
    ok_u8  = __syncthreads_and(ok_u8);
    if (t == 0) g_mask_mode = ok_i32 ? 0 : (ok_u8 ? 1 : 2);
}

// ---------------------------------------------------------------------------
// Convert fp32 -> single fp16 planes (X and W).
// ---------------------------------------------------------------------------
struct ConvArgs { const float* src[6]; };

__global__ __launch_bounds__(256) void convert_kernel(ConvArgs a) {
    const int z = blockIdx.z;
    const int tid = threadIdx.x;
    const float4* src = (const float4*)a.src[z];
    int nf8;
    unsigned short* dh;
    if (z < 3) { nf8 = XSEG / 8; dh = g_xh + (size_t)z * XSEG; }
    else       { nf8 = WSEG / 8; dh = g_wh + (size_t)(z - 3) * WSEG; }
    for (int i = blockIdx.x * 256 + tid; i < nf8; i += 1024 * 256) {
        float4 v0 = src[2 * i];
        float4 v1 = src[2 * i + 1];
        uint4 hv;
        hv.x = cvt2_f16(v0.x, v0.y);
        hv.y = cvt2_f16(v0.z, v0.w);
        hv.z = cvt2_f16(v1.x, v1.y);
        hv.w = cvt2_f16(v1.z, v1.w);
        ((uint4*)dh)[i] = hv;
    }
}

// ---------------------------------------------------------------------------
// Mask -> bf16 additive bias in FRAGMENT-MAJOR layout.
// ---------------------------------------------------------------------------
__global__ __launch_bounds__(256) void mask_conv_kernel(const void* mask) {
    const int mode = g_mask_mode;
    __nv_bfloat16 nb = __float2bfloat16(NEGINF);
    const uint32_t neg = (uint32_t)*(unsigned short*)&nb;
    const int ch = blockIdx.x * 256 + threadIdx.x;

    const int tp    = ch & 511;
    const int cpart = (ch >> 9) & 3;
    const int kt    = (ch >> 11) & 31;
    const int qb    = (ch >> 16) & 7;
    const int bz    = ch >> 19;

    const int lane = tp & 31;
    const int row  = qb * 256 + 16 * (tp >> 5) + (lane >> 2) + 8 * (cpart >> 1);
    const int col0 = kt * 64 + (cpart & 1) * 32 + 2 * (lane & 3);
    const size_t base = ((size_t)bz * S_ + row) * S_ + col0;

    unsigned m[8];
    if (mode == 0) {
        const int* mp = (const int*)mask;
#pragma unroll
        for (int j = 0; j < 4; ++j) {
            int2 v = *(const int2*)(mp + base + j * 8);
            m[2 * j]     = v.x != 0;
            m[2 * j + 1] = v.y != 0;
        }
    } else if (mode == 1) {
        const unsigned char* mp = (const unsigned char*)mask;
#pragma unroll
        for (int j = 0; j < 4; ++j) {
            unsigned short v = *(const unsigned short*)(mp + base + j * 8);
            m[2 * j]     = v & 0x00FF;
            m[2 * j + 1] = v & 0xFF00;
        }
    } else {
        const float* mp = (const float*)mask;
#pragma unroll
        for (int j = 0; j < 4; ++j) {
            float2 v = *(const float2*)(mp + base + j * 8);
            m[2 * j]     = v.x != 0.f;
            m[2 * j + 1] = v.y != 0.f;
        }
    }
    uint4 o;
    o.x = (m[0] ? neg : 0u) | ((m[1] ? neg : 0u) << 16);
    o.y = (m[2] ? neg : 0u) | ((m[3] ? neg : 0u) << 16);
    o.z = (m[4] ? neg : 0u) | ((m[5] ? neg : 0u) << 16);
    o.w = (m[6] ? neg : 0u) | ((m[7] ? neg : 0u) << 16);
    ((uint4*)g_mb)[ch] = o;
}

// ---------------------------------------------------------------------------
// Projection GEMM (R12 config): fp16 x fp16, BM=128, BN=256, BK=32,
// 512 threads (16 warps, 4m x 4n, 32x64 warp tiles), 3-stage cp.async.
// ---------------------------------------------------------------------------
#define PSTG 24576u
#define PROJ_SMEM (3u * PSTG)   // 73728

struct ProjArgs { const float* bias[3]; float scale[3]; };

__device__ __forceinline__ void proj_issue(
    uint32_t sb, int st, int kt, int tid, int m0, int n0,
    const unsigned short* Xh, const unsigned short* Wh)
{
    const uint32_t stage = sb + (uint32_t)st * PSTG;
    {
        int row = tid >> 2, c = tid & 3;
        uint32_t doff = (uint32_t)row * 64u + (uint32_t)((c ^ ((row >> 1) & 3)) << 4);
        CP16(stage + doff, Xh + (size_t)(m0 + row) * DM + kt * 32 + c * 8);
    }
#pragma unroll
    for (int j = 0; j < 2; ++j) {
        int line = tid + 512 * j;
        int row = line >> 2, c = line & 3;
        uint32_t doff = (uint32_t)row * 64u + (uint32_t)((c ^ ((row >> 1) & 3)) << 4);
        CP16(stage + 8192u + doff, Wh + (size_t)(n0 + row) * DM + kt * 32 + c * 8);
    }
    CP_COMMIT();
}

__global__ __launch_bounds__(512) void proj_mma_kernel(ProjArgs args) {
    extern __shared__ char ps[];
    const uint32_t sb = smem_u32(ps);
    const int z = blockIdx.z;
    const unsigned short* __restrict__ Xh = g_xh + (size_t)z * XSEG;
    const unsigned short* __restrict__ Wh = g_wh + (size_t)z * WSEG;
    const float* __restrict__ bias = args.bias[z];
    const float scale = args.scale[z];
    unsigned short* __restrict__ dst = (z == 0) ? g_qh : (z == 1) ? g_kh : g_vh;

    const int tid = threadIdx.x, lane = tid & 31, wid = tid >> 5;
    const int wm = wid & 3, wn = wid >> 2;
    const int m0 = blockIdx.y * 128, n0 = blockIdx.x * 256;
    const int flr = lane & 15, flc = lane >> 4;

    float C[2][8][4];
#pragma unroll
    for (int i = 0; i < 2; ++i)
#pragma unroll
        for (int j = 0; j < 8; ++j)
#pragma unroll
            for (int k = 0; k < 4; ++k) C[i][j][k] = 0.f;

    proj_issue(sb, 0, 0, tid, m0, n0, Xh, Wh);
    proj_issue(sb, 1, 1, tid, m0, n0, Xh, Wh);

    for (int kt = 0; kt < 32; ++kt) {
        if (kt < 31) CP_WAIT1(); else CP_WAIT0();
        __syncthreads();
        if (kt + 2 < 32)
            proj_issue(sb, (kt + 2) % 3, kt + 2, tid, m0, n0, Xh, Wh);

        const uint32_t base = sb + (uint32_t)(kt % 3) * PSTG;
#pragma unroll
        for (int ks = 0; ks < 2; ++ks) {
            const uint32_t csw = (uint32_t)(((2 * ks + flc) ^ ((flr >> 1) & 3)) << 4);
            uint32_t a4[2][4];
#pragma unroll
            for (int mt = 0; mt < 2; ++mt) {
                uint32_t off = (uint32_t)((32 * wm + 16 * mt + flr) * 64) + csw;
                ldsm4(base + off, a4[mt]);
            }
#pragma unroll
            for (int ntp = 0; ntp < 4; ++ntp) {
                uint32_t boff = (uint32_t)((64 * wn + 16 * ntp + flr) * 64) + csw;
                uint32_t b4[4];
                ldsm4(base + 8192u + boff, b4);
                mma16816f(C[0][2 * ntp],     a4[0], b4[0], b4[2]);
                mma16816f(C[1][2 * ntp],     a4[1], b4[0], b4[2]);
                mma16816f(C[0][2 * ntp + 1], a4[0], b4[1], b4[3]);
                mma16816f(C[1][2 * ntp + 1], a4[1], b4[1], b4[3]);
            }
        }
    }

#pragma unroll
    for (int nt = 0; nt < 8; ++nt) {
        int n = n0 + 64 * wn + 8 * nt + 2 * (lane & 3);
        int h = n >> 6, d = n & 63;
        float2 bv = *(const float2*)(bias + n);
#pragma unroll
        for (int mt = 0; mt < 2; ++mt) {
            int mbase = m0 + 32 * wm + 16 * mt + (lane >> 2);
#pragma unroll
            for (int half = 0; half < 2; ++half) {
                int m = mbase + 8 * half;
                int b = m >> 11, s = m & (S_ - 1);
                float vx = (C[mt][nt][2 * half + 0] + bv.x) * scale;
                float vy = (C[mt][nt][2 * half + 1] + bv.y) * scale;
                size_t off = ((size_t)(b * H_ + h) * S_ + s) * DH + d;
                *(uint32_t*)(dst + off) = cvt2_f16(vx, vy);
            }
        }
    }
}

// ---------------------------------------------------------------------------
// Flash attention: fp16, fragment-major mask with REGISTER PREFETCH
// (kt+1's bias loaded during kt's compute). 512 threads, 16 warps x 16 q-rows.
// Stage (16KB): K@0 | V@8K, 3 stages. Q plane @49152 (32KB). Total 81920.
// ---------------------------------------------------------------------------
#define ASTG 16384u
#define AQOFF 49152u
#define ATTN_SMEM 81920u

__device__ __forceinline__ void attn_issue_kv(uint32_t sb, int st, int kt,
                                              int tid, size_t bhS) {
#pragma unroll
    for (int j = 0; j < 2; ++j) {
        int cid = tid + 512 * j;
        int sub = cid >> 9, w = cid & 511, row = w >> 3, c = w & 7;
        const unsigned short* plane = sub ? g_vh : g_kh;
        const void* src = plane + (bhS + (size_t)(kt * 64 + row)) * DH + c * 8;
        uint32_t dst = sb + (uint32_t)st * ASTG + (uint32_t)sub * 8192u
                     + (uint32_t)row * 128u + (uint32_t)((c ^ (row & 7)) << 4);
        CP16(dst, src);
    }
    CP_COMMIT();
}

__global__ __launch_bounds__(512) void attn_mma_kernel(float* __restrict__ out)
{
    extern __shared__ char as_[];
    const uint32_t sb = smem_u32(as_);

    const int tid = threadIdx.x, lane = tid & 31, wid = tid >> 5;
    const int bz = blockIdx.z, h = blockIdx.y;
    const int qb = blockIdx.x;
    const int q0 = qb * 256;
    const size_t bhS = (size_t)(bz * H_ + h) * S_;

    const int flr = lane & 15, flc = lane >> 4;
    const int r_in = lane >> 2;
    const int c_in = 2 * (lane & 3);

    // prologue: Q plane + tiles 0,1
    {
#pragma unroll
        for (int j = 0; j < 4; ++j) {
            int cid = tid + 512 * j;
            int row = cid >> 3, c = cid & 7;
            const void* src = g_qh + (bhS + (size_t)(q0 + row)) * DH + c * 8;
            uint32_t dst = sb + AQOFF
                         + (uint32_t)row * 128u + (uint32_t)((c ^ (row & 7)) << 4);
            CP16(dst, src);
        }
    }
    attn_issue_kv(sb, 0, 0, tid, bhS);
    attn_issue_kv(sb, 1, 1, tid, bhS);

    // fragment-major mask base; prefetch tile 0's bias immediately (overlaps
    // the cp.async waits below)
    const uint4* mb4 = (const uint4*)g_mb
                     + ((size_t)(bz * 8 + qb) * 32) * 4 * 512 + tid;
    uint4 mc0 = mb4[0];
    uint4 mc1 = mb4[512];
    uint4 mc2 = mb4[1024];
    uint4 mc3 = mb4[1536];

    // wait for group 0 (Q + tile0), hoist Q fragments
    CP_WAIT1();
    __syncthreads();
    const int qrow = 16 * wid + flr;
    uint32_t qf[4][4];
#pragma unroll
    for (int ks = 0; ks < 4; ++ks) {
        uint32_t qoff = (uint32_t)(qrow * 128)
                      + (uint32_t)(((2 * ks + flc) ^ (qrow & 7)) << 4);
        ldsm4(sb + AQOFF + qoff, qf[ks]);
    }

    float oC[8][4];
#pragma unroll
    for (int j = 0; j < 8; ++j)
#pragma unroll
        for (int k = 0; k < 4; ++k) oC[j][k] = 0.f;
    float mi0 = NEGINF, mi1 = NEGINF, li0 = 0.f, li1 = 0.f;

    const int rowA0 = q0 + 16 * wid + r_in;

    for (int kt = 0; kt < 32; ++kt) {
        if (kt < 31) CP_WAIT1(); else CP_WAIT0();
        __syncthreads();
        if (kt + 2 < 32) attn_issue_kv(sb, (kt + 2) % 3, kt + 2, tid, bhS);

        const uint32_t base = sb + (uint32_t)(kt % 3) * ASTG;

        // S init from prefetched bias registers
        float sC[8][4];
        {
            uint32_t a0[4] = {mc0.x, mc0.y, mc0.z, mc0.w};
            uint32_t a1[4] = {mc1.x, mc1.y, mc1.z, mc1.w};
            uint32_t a2[4] = {mc2.x, mc2.y, mc2.z, mc2.w};
            uint32_t a3[4] = {mc3.x, mc3.y, mc3.z, mc3.w};
#pragma unroll
            for (int j = 0; j < 4; ++j) {
                sC[j][0]     = bf16lo_f(a0[j]); sC[j][1]     = bf16hi_f(a0[j]);
                sC[4 + j][0] = bf16lo_f(a1[j]); sC[4 + j][1] = bf16hi_f(a1[j]);
                sC[j][2]     = bf16lo_f(a2[j]); sC[j][3]     = bf16hi_f(a2[j]);
                sC[4 + j][2] = bf16lo_f(a3[j]); sC[4 + j][3] = bf16hi_f(a3[j]);
            }
        }
        // prefetch next tile's bias (latency hidden behind MMA/softmax below)
        if (kt + 1 < 32) {
            const uint4* mn = mb4 + (size_t)(kt + 1) * 4 * 512;
            mc0 = mn[0];
            mc1 = mn[512];
            mc2 = mn[1024];
            mc3 = mn[1536];
        }

        // -- S += Q K^T --
#pragma unroll
        for (int ks = 0; ks < 4; ++ks) {
            uint32_t k4[4][4];
#pragma unroll
            for (int ntp = 0; ntp < 4; ++ntp) {
                uint32_t koff = (uint32_t)((16 * ntp + flr) * 128)
                              + (uint32_t)(((2 * ks + flc) ^ (flr & 7)) << 4);
                ldsm4(base + koff, k4[ntp]);
            }
#pragma unroll
            for (int ntp = 0; ntp < 4; ++ntp) {
                mma16816f(sC[2 * ntp],     qf[ks], k4[ntp][0], k4[ntp][2]);
                mma16816f(sC[2 * ntp + 1], qf[ks], k4[ntp][1], k4[ntp][3]);
            }
        }

        // -- online softmax (log2 domain) --
        float mx0 = NEGINF, mx1 = NEGINF;
#pragma unroll
        for (int nt = 0; nt < 8; ++nt) {
            mx0 = fmaxf(mx0, fmaxf(sC[nt][0], sC[nt][1]));
            mx1 = fmaxf(mx1, fmaxf(sC[nt][2], sC[nt][3]));
        }
        mx0 = fmaxf(mx0, __shfl_xor_sync(0xffffffffu, mx0, 1));
        mx0 = fmaxf(mx0, __shfl_xor_sync(0xffffffffu, mx0, 2));
        mx1 = fmaxf(mx1, __shfl_xor_sync(0xffffffffu, mx1, 1));
        mx1 = fmaxf(mx1, __shfl_xor_sync(0xffffffffu, mx1, 2));

        float mn0 = fmaxf(mi0, mx0), mn1 = fmaxf(mi1, mx1);
        float f0 = ex2f(mi0 - mn0), f1 = ex2f(mi1 - mn1);
        float sum0 = 0.f, sum1 = 0.f;
#pragma unroll
        for (int nt = 0; nt < 8; ++nt) {
            sC[nt][0] = ex2f(sC[nt][0] - mn0);
            sC[nt][1] = ex2f(sC[nt][1] - mn0);
            sC[nt][2] = ex2f(sC[nt][2] - mn1);
            sC[nt][3] = ex2f(sC[nt][3] - mn1);
            sum0 += sC[nt][0] + sC[nt][1];
            sum1 += sC[nt][2] + sC[nt][3];
        }
        sum0 += __shfl_xor_sync(0xffffffffu, sum0, 1);
        sum0 += __shfl_xor_sync(0xffffffffu, sum0, 2);
        sum1 += __shfl_xor_sync(0xffffffffu, sum1, 1);
        sum1 += __shfl_xor_sync(0xffffffffu, sum1, 2);
        li0 = li0 * f0 + sum0;
        li1 = li1 * f1 + sum1;
        mi0 = mn0; mi1 = mn1;
#pragma unroll
        for (int nt = 0; nt < 8; ++nt) {
            oC[nt][0] *= f0; oC[nt][1] *= f0;
            oC[nt][2] *= f1; oC[nt][3] *= f1;
        }

        // -- O += P V --
#pragma unroll
        for (int kp = 0; kp < 4; ++kp) {
            uint32_t pa[4];
            pa[0] = cvt2_f16(sC[2 * kp][0],     sC[2 * kp][1]);
            pa[1] = cvt2_f16(sC[2 * kp][2],     sC[2 * kp][3]);
            pa[2] = cvt2_f16(sC[2 * kp + 1][0], sC[2 * kp + 1][1]);
            pa[3] = cvt2_f16(sC[2 * kp + 1][2], sC[2 * kp + 1][3]);

            const int trow = kp * 16 + ((lane >> 3) & 1) * 8 + (lane & 7);
            const int cb = lane >> 4;
            uint32_t v4[4][4];
#pragma unroll
            for (int ntp = 0; ntp < 4; ++ntp) {
                uint32_t voff = (uint32_t)(trow * 128)
                              + (uint32_t)(((2 * ntp + cb) ^ (trow & 7)) << 4);
                ldsm4t(base + 8192u + voff, v4[ntp]);
            }
#pragma unroll
            for (int ntp = 0; ntp < 4; ++ntp) {
                mma16816f(oC[2 * ntp],     pa, v4[ntp][0], v4[ntp][1]);
                mma16816f(oC[2 * ntp + 1], pa, v4[ntp][2], v4[ntp][3]);
            }
        }
    }

    // ---- epilogue ----
    float inv0 = (li0 > 0.f) ? 1.0f / li0 : 0.f;
    float inv1 = (li1 > 0.f) ? 1.0f / li1 : 0.f;
    const int qr = rowA0;
    const int d0 = h * DH + c_in;
#pragma unroll
    for (int nt = 0; nt < 8; ++nt) {
        float2 v0, v1;
        v0.x = oC[nt][0] * inv0; v0.y = oC[nt][1] * inv0;
        v1.x = oC[nt][2] * inv1; v1.y = oC[nt][3] * inv1;
        *(float2*)(out + (size_t)(bz * S_ + qr) * DM + d0 + 8 * nt) = v0;
        *(float2*)(out + (size_t)(bz * S_ + qr + 8) * DM + d0 + 8 * nt) = v1;
    }
}

// ---------------------------------------------------------------------------
extern "C" void kernel_launch(void* const* d_in, const int* in_sizes, int n_in,
                              void* d_out, int out_size) {
    const void* mask = d_in[3];
    float* out = (float*)d_out;

    static int init_done = 0;
    static cudaStream_t s2 = 0;
    static cudaEvent_t evA = 0, evB = 0;
    if (!init_done) {
        cudaFuncSetAttribute(proj_mma_kernel,
                             cudaFuncAttributeMaxDynamicSharedMemorySize, PROJ_SMEM);
        cudaFuncSetAttribute(attn_mma_kernel,
                             cudaFuncAttributeMaxDynamicSharedMemorySize, ATTN_SMEM);
        if (cudaStreamCreateWithFlags(&s2, cudaStreamNonBlocking) != cudaSuccess)
            s2 = 0;
        cudaEventCreateWithFlags(&evA, cudaEventDisableTiming);
        cudaEventCreateWithFlags(&evB, cudaEventDisableTiming);
        init_done = 1;
    }

    detect_mask_kernel<<<1, 256>>>((const unsigned int*)mask);

    cudaStream_t ms = s2 ? s2 : (cudaStream_t)0;
    if (s2) {
        cudaEventRecord(evA, 0);
        cudaStreamWaitEvent(s2, evA, 0);
    }
    mask_conv_kernel<<<4096, 256, 0, ms>>>(mask);
    if (s2) cudaEventRecord(evB, s2);

    ConvArgs ca;
    ca.src[0] = (const float*)d_in[0];
    ca.src[1] = (const float*)d_in[1];
    ca.src[2] = (const float*)d_in[2];
    ca.src[3] = (const float*)d_in[4];
    ca.src[4] = (const float*)d_in[6];
    ca.src[5] = (const float*)d_in[8];
    convert_kernel<<<dim3(1024, 1, 6), 256>>>(ca);

    ProjArgs pa;
    pa.bias[0] = (const float*)d_in[5];
    pa.bias[1] = (const float*)d_in[7];
    pa.bias[2] = (const float*)d_in[9];
    pa.scale[0] = QSCALE; pa.scale[1] = 1.0f; pa.scale[2] = 1.0f;
    proj_mma_kernel<<<dim3(4, 32, 3), 512, PROJ_SMEM>>>(pa);

    if (s2) cudaStreamWaitEvent(0, evB, 0);
    attn_mma_kernel<<<dim3(8, 16, 2), 512, ATTN_SMEM>>>(out);
}

// round 15
// speedup vs baseline: 1.3063x; 1.0156x over previous
#include <cuda_runtime.h>
#include <cuda_bf16.h>
#include <cuda_fp16.h>
#include <cstdint>
#include <cstddef>

#define B_  2
#define S_  2048
#define DM  1024
#define H_  16
#define DH  64
#define M_  (B_*S_)   // 4096
#define NEGINF -1e30f
#define QSCALE (0.125f * 1.44269504088896f)

#define XSEG (M_*DM)
#define WSEG (DM*DM)
#define QKV  (B_*H_*S_*DH)

__device__ unsigned short g_xh[3*XSEG];                 // X: single fp16
__device__ unsigned short g_wh[3*WSEG];                 // W: single fp16
__device__ unsigned short g_qh[QKV];                    // Q: single fp16 (scaled)
__device__ unsigned short g_kh[QKV];                    // K: single fp16
__device__ unsigned short g_vh[QKV];                    // V: single fp16
// mask bias, FRAGMENT-MAJOR for 128-row q-blocks: uint4 chunk index =
//   ((((bz*16+qb)*32 + kt)*4 + cpart)*256 + tid)
__device__ unsigned short g_mb[(size_t)B_*S_*S_];
__device__ int g_mask_mode;

// ---------------------------------------------------------------------------
__device__ __forceinline__ uint32_t smem_u32(const void* p) {
    uint32_t a;
    asm("{ .reg .u64 t; cvta.to.shared.u64 t, %1; cvt.u32.u64 %0, t; }"
        : "=r"(a) : "l"(p));
    return a;
}
__device__ __forceinline__ void ldsm4(uint32_t addr, uint32_t* r) {
    asm volatile("ldmatrix.sync.aligned.m8n8.x4.shared.b16 {%0,%1,%2,%3}, [%4];"
        : "=r"(r[0]), "=r"(r[1]), "=r"(r[2]), "=r"(r[3]) : "r"(addr));
}
__device__ __forceinline__ void ldsm4t(uint32_t addr, uint32_t* r) {
    asm volatile("ldmatrix.sync.aligned.m8n8.x4.trans.shared.b16 {%0,%1,%2,%3}, [%4];"
        : "=r"(r[0]), "=r"(r[1]), "=r"(r[2]), "=r"(r[3]) : "r"(addr));
}
__device__ __forceinline__ void mma16816f(float* c, const uint32_t* a,
                                          uint32_t b0, uint32_t b1) {
    asm volatile(
        "mma.sync.aligned.m16n8k16.row.col.f32.f16.f16.f32 "
        "{%0,%1,%2,%3}, {%4,%5,%6,%7}, {%8,%9}, {%0,%1,%2,%3};"
        : "+f"(c[0]), "+f"(c[1]), "+f"(c[2]), "+f"(c[3])
        : "r"(a[0]), "r"(a[1]), "r"(a[2]), "r"(a[3]), "r"(b0), "r"(b1));
}
__device__ __forceinline__ uint32_t cvt2_f16(float lo_elem, float hi_elem) {
    uint32_t r;
    asm("cvt.rn.f16x2.f32 %0, %1, %2;" : "=r"(r) : "f"(hi_elem), "f"(lo_elem));
    return r;
}
__device__ __forceinline__ float bf16lo_f(uint32_t v) { return __uint_as_float(v << 16); }
__device__ __forceinline__ float bf16hi_f(uint32_t v) { return __uint_as_float(v & 0xFFFF0000u); }
__device__ __forceinline__ float ex2f(float x) {
    float y;
    asm("ex2.approx.f32 %0, %1;" : "=f"(y) : "f"(x));
    return y;
}
#define CP16(dst, src) \
    asm volatile("cp.async.cg.shared.global [%0], [%1], 16;" :: "r"(dst), "l"(src))
#define CP_COMMIT() asm volatile("cp.async.commit_group;")
#define CP_WAIT2()  asm volatile("cp.async.wait_group 2;")
#define CP_WAIT1()  asm volatile("cp.async.wait_group 1;")
#define CP_WAIT0()  asm volatile("cp.async.wait_group 0;")

// ---------------------------------------------------------------------------
// Mask dtype detection (runs on side stream, overlapped with convert).
// ---------------------------------------------------------------------------
__global__ void detect_mask_kernel(const unsigned int* __restrict__ m) {
    int t = threadIdx.x;
    int ok_i32 = 1, ok_u8 = 1;
    for (int i = t; i < 4096; i += 256) {
        unsigned w = m[i];
        ok_i32 &= (w <= 1u);
        ok_u8  &= ((w & 0xFEFEFEFEu) == 0u);
    }
    ok_i32 = __syncthreads_and(ok_i32);
    ok_u8  = __syncthreads_and(ok_u8);
    if (t == 0) g_mask_mode = ok_i32 ? 0 : (ok_u8 ? 1 : 2);
}

// ---------------------------------------------------------------------------
// Convert fp32 -> single fp16 planes (X and W).
// ---------------------------------------------------------------------------
struct ConvArgs { const float* src[6]; };

__global__ __launch_bounds__(256) void convert_kernel(ConvArgs a) {
    const int z = blockIdx.z;
    const int tid = threadIdx.x;
    const float4* src = (const float4*)a.src[z];
    int nf8;
    unsigned short* dh;
    if (z < 3) { nf8 = XSEG / 8; dh = g_xh + (size_t)z * XSEG; }
    else       { nf8 = WSEG / 8; dh = g_wh + (size_t)(z - 3) * WSEG; }
    for (int i = blockIdx.x * 256 + tid; i < nf8; i += 1024 * 256) {
        float4 v0 = src[2 * i];
        float4 v1 = src[2 * i + 1];
        uint4 hv;
        hv.x = cvt2_f16(v0.x, v0.y);
        hv.y = cvt2_f16(v0.z, v0.w);
        hv.z = cvt2_f16(v1.x, v1.y);
        hv.w = cvt2_f16(v1.z, v1.w);
        ((uint4*)dh)[i] = hv;
    }
}

// ---------------------------------------------------------------------------
// Mask -> bf16 additive bias, FRAGMENT-MAJOR (128-row q-blocks).
// ch bits: tid=ch&255, cpart=(ch>>8)&3, kt=(ch>>10)&31, qb=(ch>>15)&15,
//          bz=(ch>>19)&1.
// ---------------------------------------------------------------------------
__global__ __launch_bounds__(256) void mask_conv_kernel(const void* mask) {
    const int mode = g_mask_mode;
    __nv_bfloat16 nb = __float2bfloat16(NEGINF);
    const uint32_t neg = (uint32_t)*(unsigned short*)&nb;
    const int ch = blockIdx.x * 256 + threadIdx.x;

    const int tp    = ch & 255;
    const int cpart = (ch >> 8) & 3;
    const int kt    = (ch >> 10) & 31;
    const int qb    = (ch >> 15) & 15;
    const int bz    = (ch >> 19) & 1;

    const int lane = tp & 31;
    const int row  = qb * 128 + 16 * (tp >> 5) + (lane >> 2) + 8 * (cpart >> 1);
    const int col0 = kt * 64 + (cpart & 1) * 32 + 2 * (lane & 3);
    const size_t base = ((size_t)bz * S_ + row) * S_ + col0;

    unsigned m[8];
    if (mode == 0) {
        const int* mp = (const int*)mask;
#pragma unroll
        for (int j = 0; j < 4; ++j) {
            int2 v = *(const int2*)(mp + base + j * 8);
            m[2 * j]     = v.x != 0;
            m[2 * j + 1] = v.y != 0;
        }
    } else if (mode == 1) {
        const unsigned char* mp = (const unsigned char*)mask;
#pragma unroll
        for (int j = 0; j < 4; ++j) {
            unsigned short v = *(const unsigned short*)(mp + base + j * 8);
            m[2 * j]     = v & 0x00FF;
            m[2 * j + 1] = v & 0xFF00;
        }
    } else {
        const float* mp = (const float*)mask;
#pragma unroll
        for (int j = 0; j < 4; ++j) {
            float2 v = *(const float2*)(mp + base + j * 8);
            m[2 * j]     = v.x != 0.f;
            m[2 * j + 1] = v.y != 0.f;
        }
    }
    uint4 o;
    o.x = (m[0] ? neg : 0u) | ((m[1] ? neg : 0u) << 16);
    o.y = (m[2] ? neg : 0u) | ((m[3] ? neg : 0u) << 16);
    o.z = (m[4] ? neg : 0u) | ((m[5] ? neg : 0u) << 16);
    o.w = (m[6] ? neg : 0u) | ((m[7] ? neg : 0u) << 16);
    ((uint4*)g_mb)[ch] = o;
}

// ---------------------------------------------------------------------------
// Projection GEMM: fp16 x fp16, BM=128, BN=256, BK=32, 512 threads
// (16 warps, 4m x 4n, 32x64 warp tiles), 4-stage cp.async.
// ---------------------------------------------------------------------------
#define PSTG 24576u
#define PROJ_SMEM (4u * PSTG)   // 98304

struct ProjArgs { const float* bias[3]; float scale[3]; };

__device__ __forceinline__ void proj_issue(
    uint32_t sb, int st, int kt, int tid, int m0, int n0,
    const unsigned short* Xh, const unsigned short* Wh)
{
    const uint32_t stage = sb + (uint32_t)st * PSTG;
    {
        int row = tid >> 2, c = tid & 3;
        uint32_t doff = (uint32_t)row * 64u + (uint32_t)((c ^ ((row >> 1) & 3)) << 4);
        CP16(stage + doff, Xh + (size_t)(m0 + row) * DM + kt * 32 + c * 8);
    }
#pragma unroll
    for (int j = 0; j < 2; ++j) {
        int line = tid + 512 * j;
        int row = line >> 2, c = line & 3;
        uint32_t doff = (uint32_t)row * 64u + (uint32_t)((c ^ ((row >> 1) & 3)) << 4);
        CP16(stage + 8192u + doff, Wh + (size_t)(n0 + row) * DM + kt * 32 + c * 8);
    }
    CP_COMMIT();
}

__global__ __launch_bounds__(512) void proj_mma_kernel(ProjArgs args) {
    extern __shared__ char ps[];
    const uint32_t sb = smem_u32(ps);
    const int z = blockIdx.z;
    const unsigned short* __restrict__ Xh = g_xh + (size_t)z * XSEG;
    const unsigned short* __restrict__ Wh = g_wh + (size_t)z * WSEG;
    const float* __restrict__ bias = args.bias[z];
    const float scale = args.scale[z];
    unsigned short* __restrict__ dst = (z == 0) ? g_qh : (z == 1) ? g_kh : g_vh;

    const int tid = threadIdx.x, lane = tid & 31, wid = tid >> 5;
    const int wm = wid & 3, wn = wid >> 2;
    const int m0 = blockIdx.y * 128, n0 = blockIdx.x * 256;
    const int flr = lane & 15, flc = lane >> 4;

    float C[2][8][4];
#pragma unroll
    for (int i = 0; i < 2; ++i)
#pragma unroll
        for (int j = 0; j < 8; ++j)
#pragma unroll
            for (int k = 0; k < 4; ++k) C[i][j][k] = 0.f;

    proj_issue(sb, 0, 0, tid, m0, n0, Xh, Wh);
    proj_issue(sb, 1, 1, tid, m0, n0, Xh, Wh);
    proj_issue(sb, 2, 2, tid, m0, n0, Xh, Wh);

    for (int kt = 0; kt < 32; ++kt) {
        if (kt < 30) CP_WAIT2(); else if (kt < 31) CP_WAIT1(); else CP_WAIT0();
        __syncthreads();
        if (kt + 3 < 32)
            proj_issue(sb, (kt + 3) & 3, kt + 3, tid, m0, n0, Xh, Wh);

        const uint32_t base = sb + (uint32_t)(kt & 3) * PSTG;
#pragma unroll
        for (int ks = 0; ks < 2; ++ks) {
            const uint32_t csw = (uint32_t)(((2 * ks + flc) ^ ((flr >> 1) & 3)) << 4);
            uint32_t a4[2][4];
#pragma unroll
            for (int mt = 0; mt < 2; ++mt) {
                uint32_t off = (uint32_t)((32 * wm + 16 * mt + flr) * 64) + csw;
                ldsm4(base + off, a4[mt]);
            }
#pragma unroll
            for (int ntp = 0; ntp < 4; ++ntp) {
                uint32_t boff = (uint32_t)((64 * wn + 16 * ntp + flr) * 64) + csw;
                uint32_t b4[4];
                ldsm4(base + 8192u + boff, b4);
                mma16816f(C[0][2 * ntp],     a4[0], b4[0], b4[2]);
                mma16816f(C[1][2 * ntp],     a4[1], b4[0], b4[2]);
                mma16816f(C[0][2 * ntp + 1], a4[0], b4[1], b4[3]);
                mma16816f(C[1][2 * ntp + 1], a4[1], b4[1], b4[3]);
            }
        }
    }

#pragma unroll
    for (int nt = 0; nt < 8; ++nt) {
        int n = n0 + 64 * wn + 8 * nt + 2 * (lane & 3);
        int h = n >> 6, d = n & 63;
        float2 bv = *(const float2*)(bias + n);
#pragma unroll
        for (int mt = 0; mt < 2; ++mt) {
            int mbase = m0 + 32 * wm + 16 * mt + (lane >> 2);
#pragma unroll
            for (int half = 0; half < 2; ++half) {
                int m = mbase + 8 * half;
                int b = m >> 11, s = m & (S_ - 1);
                float vx = (C[mt][nt][2 * half + 0] + bv.x) * scale;
                float vy = (C[mt][nt][2 * half + 1] + bv.y) * scale;
                size_t off = ((size_t)(b * H_ + h) * S_ + s) * DH + d;
                *(uint32_t*)(dst + off) = cvt2_f16(vx, vy);
            }
        }
    }
}

// ---------------------------------------------------------------------------
// Flash attention: fp16, 256 threads (8 warps x 16 q-rows = 128 q-rows/CTA),
// 2 CTAs/SM. 3-stage cp.async K/V + register-prefetched fragment-major mask.
// Stage (16KB): K@0 | V@8K. Q plane @49152 (16KB). Total 65536.
// ---------------------------------------------------------------------------
#define ASTG 16384u
#define AQOFF 49152u
#define ATTN_SMEM 65536u

__device__ __forceinline__ void attn_issue_kv(uint32_t sb, int st, int kt,
                                              int tid, size_t bhS) {
#pragma unroll
    for (int j = 0; j < 4; ++j) {
        int cid = tid + 256 * j;
        int sub = cid >> 9, w = cid & 511, row = w >> 3, c = w & 7;
        const unsigned short* plane = sub ? g_vh : g_kh;
        const void* src = plane + (bhS + (size_t)(kt * 64 + row)) * DH + c * 8;
        uint32_t dst = sb + (uint32_t)st * ASTG + (uint32_t)sub * 8192u
                     + (uint32_t)row * 128u + (uint32_t)((c ^ (row & 7)) << 4);
        CP16(dst, src);
    }
    CP_COMMIT();
}

__global__ __launch_bounds__(256, 2) void attn_mma_kernel(float* __restrict__ out)
{
    extern __shared__ char as_[];
    const uint32_t sb = smem_u32(as_);

    const int tid = threadIdx.x, lane = tid & 31, wid = tid >> 5;
    const int bz = blockIdx.z, h = blockIdx.y;
    const int qb = blockIdx.x;
    const int q0 = qb * 128;
    const size_t bhS = (size_t)(bz * H_ + h) * S_;

    const int flr = lane & 15, flc = lane >> 4;
    const int r_in = lane >> 2;
    const int c_in = 2 * (lane & 3);

    // prologue: Q plane (128 rows = 1024 lines) + tiles 0,1
    {
#pragma unroll
        for (int j = 0; j < 4; ++j) {
            int cid = tid + 256 * j;
            int row = cid >> 3, c = cid & 7;
            const void* src = g_qh + (bhS + (size_t)(q0 + row)) * DH + c * 8;
            uint32_t dst = sb + AQOFF
                         + (uint32_t)row * 128u + (uint32_t)((c ^ (row & 7)) << 4);
            CP16(dst, src);
        }
    }
    attn_issue_kv(sb, 0, 0, tid, bhS);
    attn_issue_kv(sb, 1, 1, tid, bhS);

    // fragment-major mask base; prefetch tile 0's bias
    const uint4* mb4 = (const uint4*)g_mb
                     + ((size_t)(bz * 16 + qb) * 32) * 4 * 256 + tid;
    uint4 mc0 = mb4[0];
    uint4 mc1 = mb4[256];
    uint4 mc2 = mb4[512];
    uint4 mc3 = mb4[768];

    // wait for group 0 (Q + tile0), hoist Q fragments
    CP_WAIT1();
    __syncthreads();
    const int qrow = 16 * wid + flr;
    uint32_t qf[4][4];
#pragma unroll
    for (int ks = 0; ks < 4; ++ks) {
        uint32_t qoff = (uint32_t)(qrow * 128)
                      + (uint32_t)(((2 * ks + flc) ^ (qrow & 7)) << 4);
        ldsm4(sb + AQOFF + qoff, qf[ks]);
    }

    float oC[8][4];
#pragma unroll
    for (int j = 0; j < 8; ++j)
#pragma unroll
        for (int k = 0; k < 4; ++k) oC[j][k] = 0.f;
    float mi0 = NEGINF, mi1 = NEGINF, li0 = 0.f, li1 = 0.f;

    const int rowA0 = q0 + 16 * wid + r_in;

    for (int kt = 0; kt < 32; ++kt) {
        if (kt < 31) CP_WAIT1(); else CP_WAIT0();
        __syncthreads();
        if (kt + 2 < 32) attn_issue_kv(sb, (kt + 2) % 3, kt + 2, tid, bhS);

        const uint32_t base = sb + (uint32_t)(kt % 3) * ASTG;

        // S init from prefetched bias registers
        float sC[8][4];
        {
            uint32_t a0[4] = {mc0.x, mc0.y, mc0.z, mc0.w};
            uint32_t a1[4] = {mc1.x, mc1.y, mc1.z, mc1.w};
            uint32_t a2[4] = {mc2.x, mc2.y, mc2.z, mc2.w};
            uint32_t a3[4] = {mc3.x, mc3.y, mc3.z, mc3.w};
#pragma unroll
            for (int j = 0; j < 4; ++j) {
                sC[j][0]     = bf16lo_f(a0[j]); sC[j][1]     = bf16hi_f(a0[j]);
                sC[4 + j][0] = bf16lo_f(a1[j]); sC[4 + j][1] = bf16hi_f(a1[j]);
                sC[j][2]     = bf16lo_f(a2[j]); sC[j][3]     = bf16hi_f(a2[j]);
                sC[4 + j][2] = bf16lo_f(a3[j]); sC[4 + j][3] = bf16hi_f(a3[j]);
            }
        }
        // prefetch next tile's bias
        if (kt + 1 < 32) {
            const uint4* mn = mb4 + (size_t)(kt + 1) * 4 * 256;
            mc0 = mn[0];
            mc1 = mn[256];
            mc2 = mn[512];
            mc3 = mn[768];
        }

        // -- S += Q K^T --
#pragma unroll
        for (int ks = 0; ks < 4; ++ks) {
            uint32_t k4[4][4];
#pragma unroll
            for (int ntp = 0; ntp < 4; ++ntp) {
                uint32_t koff = (uint32_t)((16 * ntp + flr) * 128)
                              + (uint32_t)(((2 * ks + flc) ^ (flr & 7)) << 4);
                ldsm4(base + koff, k4[ntp]);
            }
#pragma unroll
            for (int ntp = 0; ntp < 4; ++ntp) {
                mma16816f(sC[2 * ntp],     qf[ks], k4[ntp][0], k4[ntp][2]);
                mma16816f(sC[2 * ntp + 1], qf[ks], k4[ntp][1], k4[ntp][3]);
            }
        }

        // -- online softmax (log2 domain) --
        float mx0 = NEGINF, mx1 = NEGINF;
#pragma unroll
        for (int nt = 0; nt < 8; ++nt) {
            mx0 = fmaxf(mx0, fmaxf(sC[nt][0], sC[nt][1]));
            mx1 = fmaxf(mx1, fmaxf(sC[nt][2], sC[nt][3]));
        }
        mx0 = fmaxf(mx0, __shfl_xor_sync(0xffffffffu, mx0, 1));
        mx0 = fmaxf(mx0, __shfl_xor_sync(0xffffffffu, mx0, 2));
        mx1 = fmaxf(mx1, __shfl_xor_sync(0xffffffffu, mx1, 1));
        mx1 = fmaxf(mx1, __shfl_xor_sync(0xffffffffu, mx1, 2));

        float mn0 = fmaxf(mi0, mx0), mn1 = fmaxf(mi1, mx1);
        float f0 = ex2f(mi0 - mn0), f1 = ex2f(mi1 - mn1);
        float sum0 = 0.f, sum1 = 0.f;
#pragma unroll
        for (int nt = 0; nt < 8; ++nt) {
            sC[nt][0] = ex2f(sC[nt][0] - mn0);
            sC[nt][1] = ex2f(sC[nt][1] - mn0);
            sC[nt][2] = ex2f(sC[nt][2] - mn1);
            sC[nt][3] = ex2f(sC[nt][3] - mn1);
            sum0 += sC[nt][0] + sC[nt][1];
            sum1 += sC[nt][2] + sC[nt][3];
        }
        sum0 += __shfl_xor_sync(0xffffffffu, sum0, 1);
        sum0 += __shfl_xor_sync(0xffffffffu, sum0, 2);
        sum1 += __shfl_xor_sync(0xffffffffu, sum1, 1);
        sum1 += __shfl_xor_sync(0xffffffffu, sum1, 2);
        li0 = li0 * f0 + sum0;
        li1 = li1 * f1 + sum1;
        mi0 = mn0; mi1 = mn1;
#pragma unroll
        for (int nt = 0; nt < 8; ++nt) {
            oC[nt][0] *= f0; oC[nt][1] *= f0;
            oC[nt][2] *= f1; oC[nt][3] *= f1;
        }

        // -- O += P V --
#pragma unroll
        for (int kp = 0; kp < 4; ++kp) {
            uint32_t pa[4];
            pa[0] = cvt2_f16(sC[2 * kp][0],     sC[2 * kp][1]);
            pa[1] = cvt2_f16(sC[2 * kp][2],     sC[2 * kp][3]);
            pa[2] = cvt2_f16(sC[2 * kp + 1][0], sC[2 * kp + 1][1]);
            pa[3] = cvt2_f16(sC[2 * kp + 1][2], sC[2 * kp + 1][3]);

            const int trow = kp * 16 + ((lane >> 3) & 1) * 8 + (lane & 7);
            const int cb = lane >> 4;
            uint32_t v4[4][4];
#pragma unroll
            for (int ntp = 0; ntp < 4; ++ntp) {
                uint32_t voff = (uint32_t)(trow * 128)
                              + (uint32_t)(((2 * ntp + cb) ^ (trow & 7)) << 4);
                ldsm4t(base + 8192u + voff, v4[ntp]);
            }
#pragma unroll
            for (int ntp = 0; ntp < 4; ++ntp) {
                mma16816f(oC[2 * ntp],     pa, v4[ntp][0], v4[ntp][1]);
                mma16816f(oC[2 * ntp + 1], pa, v4[ntp][2], v4[ntp][3]);
            }
        }
    }

    // ---- epilogue ----
    float inv0 = (li0 > 0.f) ? 1.0f / li0 : 0.f;
    float inv1 = (li1 > 0.f) ? 1.0f / li1 : 0.f;
    const int qr = rowA0;
    const int d0 = h * DH + c_in;
#pragma unroll
    for (int nt = 0; nt < 8; ++nt) {
        float2 v0, v1;
        v0.x = oC[nt][0] * inv0; v0.y = oC[nt][1] * inv0;
        v1.x = oC[nt][2] * inv1; v1.y = oC[nt][3] * inv1;
        *(float2*)(out + (size_t)(bz * S_ + qr) * DM + d0 + 8 * nt) = v0;
        *(float2*)(out + (size_t)(bz * S_ + qr + 8) * DM + d0 + 8 * nt) = v1;
    }
}

// ---------------------------------------------------------------------------
extern "C" void kernel_launch(void* const* d_in, const int* in_sizes, int n_in,
                              void* d_out, int out_size) {
    const void* mask = d_in[3];
    float* out = (float*)d_out;

    static int init_done = 0;
    static cudaStream_t s2 = 0;
    static cudaEvent_t evA = 0, evB = 0;
    if (!init_done) {
        cudaFuncSetAttribute(proj_mma_kernel,
                             cudaFuncAttributeMaxDynamicSharedMemorySize, PROJ_SMEM);
        cudaFuncSetAttribute(attn_mma_kernel,
                             cudaFuncAttributeMaxDynamicSharedMemorySize, ATTN_SMEM);
        if (cudaStreamCreateWithFlags(&s2, cudaStreamNonBlocking) != cudaSuccess)
            s2 = 0;
        cudaEventCreateWithFlags(&evA, cudaEventDisableTiming);
        cudaEventCreateWithFlags(&evB, cudaEventDisableTiming);
        init_done = 1;
    }

    // fork: detect + mask_conv on side stream, overlapping convert + proj
    cudaStream_t ms = s2 ? s2 : (cudaStream_t)0;
    if (s2) {
        cudaEventRecord(evA, 0);
        cudaStreamWaitEvent(s2, evA, 0);
    }
    detect_mask_kernel<<<1, 256, 0, ms>>>((const unsigned int*)mask);
    mask_conv_kernel<<<4096, 256, 0, ms>>>(mask);
    if (s2) cudaEventRecord(evB, s2);

    ConvArgs ca;
    ca.src[0] = (const float*)d_in[0];
    ca.src[1] = (const float*)d_in[1];
    ca.src[2] = (const float*)d_in[2];
    ca.src[3] = (const float*)d_in[4];
    ca.src[4] = (const float*)d_in[6];
    ca.src[5] = (const float*)d_in[8];
    convert_kernel<<<dim3(1024, 1, 6), 256>>>(ca);

    ProjArgs pa;
    pa.bias[0] = (const float*)d_in[5];
    pa.bias[1] = (const float*)d_in[7];
    pa.bias[2] = (const float*)d_in[9];
    pa.scale[0] = QSCALE; pa.scale[1] = 1.0f; pa.scale[2] = 1.0f;
    proj_mma_kernel<<<dim3(4, 32, 3), 512, PROJ_SMEM>>>(pa);

    if (s2) cudaStreamWaitEvent(0, evB, 0);
    attn_mma_kernel<<<dim3(16, 16, 2), 256, ATTN_SMEM>>>(out);
}

// round 17
// speedup vs baseline: 1.3762x; 1.0535x over previous
#include <cuda_runtime.h>
#include <cuda_bf16.h>
#include <cuda_fp16.h>
#include <cstdint>
#include <cstddef>

#define B_  2
#define S_  2048
#define DM  1024
#define H_  16
#define DH  64
#define M_  (B_*S_)   // 4096
#define NEGINF -1e30f
#define QSCALE (0.125f * 1.44269504088896f)

#define XSEG (M_*DM)
#define WSEG (DM*DM)
#define QKV  (B_*H_*S_*DH)

__device__ unsigned short g_xh[3*XSEG];                 // X: single fp16
__device__ unsigned short g_wh[3*WSEG];                 // W: single fp16
__device__ unsigned short g_qh[QKV];                    // Q: single fp16 (scaled)
__device__ unsigned short g_kh[QKV];                    // K: single fp16
__device__ unsigned short g_vh[QKV];                    // V: single fp16
// mask bias, FRAGMENT-MAJOR for 128-row q-blocks: uint4 chunk index =
//   ((((bz*16+qb)*32 + kt)*4 + cpart)*256 + tid)
__device__ unsigned short g_mb[(size_t)B_*S_*S_];
__device__ int g_mask_mode;

// ---------------------------------------------------------------------------
__device__ __forceinline__ uint32_t smem_u32(const void* p) {
    uint32_t a;
    asm("{ .reg .u64 t; cvta.to.shared.u64 t, %1; cvt.u32.u64 %0, t; }"
        : "=r"(a) : "l"(p));
    return a;
}
__device__ __forceinline__ void ldsm4(uint32_t addr, uint32_t* r) {
    asm volatile("ldmatrix.sync.aligned.m8n8.x4.shared.b16 {%0,%1,%2,%3}, [%4];"
        : "=r"(r[0]), "=r"(r[1]), "=r"(r[2]), "=r"(r[3]) : "r"(addr));
}
__device__ __forceinline__ void ldsm4t(uint32_t addr, uint32_t* r) {
    asm volatile("ldmatrix.sync.aligned.m8n8.x4.trans.shared.b16 {%0,%1,%2,%3}, [%4];"
        : "=r"(r[0]), "=r"(r[1]), "=r"(r[2]), "=r"(r[3]) : "r"(addr));
}
__device__ __forceinline__ void mma16816f(float* c, const uint32_t* a,
                                          uint32_t b0, uint32_t b1) {
    asm volatile(
        "mma.sync.aligned.m16n8k16.row.col.f32.f16.f16.f32 "
        "{%0,%1,%2,%3}, {%4,%5,%6,%7}, {%8,%9}, {%0,%1,%2,%3};"
        : "+f"(c[0]), "+f"(c[1]), "+f"(c[2]), "+f"(c[3])
        : "r"(a[0]), "r"(a[1]), "r"(a[2]), "r"(a[3]), "r"(b0), "r"(b1));
}
__device__ __forceinline__ uint32_t cvt2_f16(float lo_elem, float hi_elem) {
    uint32_t r;
    asm("cvt.rn.f16x2.f32 %0, %1, %2;" : "=r"(r) : "f"(hi_elem), "f"(lo_elem));
    return r;
}
__device__ __forceinline__ float bf16lo_f(uint32_t v) { return __uint_as_float(v << 16); }
__device__ __forceinline__ float bf16hi_f(uint32_t v) { return __uint_as_float(v & 0xFFFF0000u); }
__device__ __forceinline__ float ex2f(float x) {
    float y;
    asm("ex2.approx.f32 %0, %1;" : "=f"(y) : "f"(x));
    return y;
}
#define CP16(dst, src) \
    asm volatile("cp.async.cg.shared.global [%0], [%1], 16;" :: "r"(dst), "l"(src))
#define CP_COMMIT() asm volatile("cp.async.commit_group;")
#define CP_WAIT2()  asm volatile("cp.async.wait_group 2;")
#define CP_WAIT1()  asm volatile("cp.async.wait_group 1;")
#define CP_WAIT0()  asm volatile("cp.async.wait_group 0;")

// ---------------------------------------------------------------------------
// Mask dtype detection.
// ---------------------------------------------------------------------------
__global__ void detect_mask_kernel(const unsigned int* __restrict__ m) {
    int t = threadIdx.x;
    int ok_i32 = 1, ok_u8 = 1;
    for (int i = t; i < 4096; i += 256) {
        unsigned w = m[i];
        ok_i32 &= (w <= 1u);
        ok_u8  &= ((w & 0xFEFEFEFEu) == 0u);
    }
    ok_i32 = __syncthreads_and(ok_i32);
    ok_u8  = __syncthreads_and(ok_u8);
    if (t == 0) g_mask_mode = ok_i32 ? 0 : (ok_u8 ? 1 : 2);
}

// ---------------------------------------------------------------------------
// Convert one projection's inputs: blockIdx.z==0 -> X slice, ==1 -> W slice.
// ---------------------------------------------------------------------------
__global__ __launch_bounds__(256) void convert_pair_kernel(
    const float* __restrict__ X, const float* __restrict__ W, int zidx)
{
    const int isW = blockIdx.z;
    const float4* src = (const float4*)(isW ? W : X);
    const int nf8 = isW ? (WSEG / 8) : (XSEG / 8);
    unsigned short* dh = isW ? (g_wh + (size_t)zidx * WSEG)
                             : (g_xh + (size_t)zidx * XSEG);
    for (int i = blockIdx.x * 256 + threadIdx.x; i < nf8; i += 512 * 256) {
        float4 v0 = src[2 * i];
        float4 v1 = src[2 * i + 1];
        uint4 hv;
        hv.x = cvt2_f16(v0.x, v0.y);
        hv.y = cvt2_f16(v0.z, v0.w);
        hv.z = cvt2_f16(v1.x, v1.y);
        hv.w = cvt2_f16(v1.z, v1.w);
        ((uint4*)dh)[i] = hv;
    }
}

// ---------------------------------------------------------------------------
// Mask -> bf16 additive bias, FRAGMENT-MAJOR (128-row q-blocks).
// ---------------------------------------------------------------------------
__global__ __launch_bounds__(256) void mask_conv_kernel(const void* mask) {
    const int mode = g_mask_mode;
    __nv_bfloat16 nb = __float2bfloat16(NEGINF);
    const uint32_t neg = (uint32_t)*(unsigned short*)&nb;
    const int ch = blockIdx.x * 256 + threadIdx.x;

    const int tp    = ch & 255;
    const int cpart = (ch >> 8) & 3;
    const int kt    = (ch >> 10) & 31;
    const int qb    = (ch >> 15) & 15;
    const int bz    = (ch >> 19) & 1;

    const int lane = tp & 31;
    const int row  = qb * 128 + 16 * (tp >> 5) + (lane >> 2) + 8 * (cpart >> 1);
    const int col0 = kt * 64 + (cpart & 1) * 32 + 2 * (lane & 3);
    const size_t base = ((size_t)bz * S_ + row) * S_ + col0;

    unsigned m[8];
    if (mode == 0) {
        const int* mp = (const int*)mask;
#pragma unroll
        for (int j = 0; j < 4; ++j) {
            int2 v = *(const int2*)(mp + base + j * 8);
            m[2 * j]     = v.x != 0;
            m[2 * j + 1] = v.y != 0;
        }
    } else if (mode == 1) {
        const unsigned char* mp = (const unsigned char*)mask;
#pragma unroll
        for (int j = 0; j < 4; ++j) {
            unsigned short v = *(const unsigned short*)(mp + base + j * 8);
            m[2 * j]     = v & 0x00FF;
            m[2 * j + 1] = v & 0xFF00;
        }
    } else {
        const float* mp = (const float*)mask;
#pragma unroll
        for (int j = 0; j < 4; ++j) {
            float2 v = *(const float2*)(mp + base + j * 8);
            m[2 * j]     = v.x != 0.f;
            m[2 * j + 1] = v.y != 0.f;
        }
    }
    uint4 o;
    o.x = (m[0] ? neg : 0u) | ((m[1] ? neg : 0u) << 16);
    o.y = (m[2] ? neg : 0u) | ((m[3] ? neg : 0u) << 16);
    o.z = (m[4] ? neg : 0u) | ((m[5] ? neg : 0u) << 16);
    o.w = (m[6] ? neg : 0u) | ((m[7] ? neg : 0u) << 16);
    ((uint4*)g_mb)[ch] = o;
}

// ---------------------------------------------------------------------------
// Projection GEMM: fp16 x fp16, BM=128, BN=256, BK=32, 512 threads
// (16 warps, 4m x 4n, 32x64 warp tiles), 4-stage cp.async. Per-z launch.
// ---------------------------------------------------------------------------
#define PSTG 24576u
#define PROJ_SMEM (4u * PSTG)   // 98304

__device__ __forceinline__ void proj_issue(
    uint32_t sb, int st, int kt, int tid, int m0, int n0,
    const unsigned short* Xh, const unsigned short* Wh)
{
    const uint32_t stage = sb + (uint32_t)st * PSTG;
    {
        int row = tid >> 2, c = tid & 3;
        uint32_t doff = (uint32_t)row * 64u + (uint32_t)((c ^ ((row >> 1) & 3)) << 4);
        CP16(stage + doff, Xh + (size_t)(m0 + row) * DM + kt * 32 + c * 8);
    }
#pragma unroll
    for (int j = 0; j < 2; ++j) {
        int line = tid + 512 * j;
        int row = line >> 2, c = line & 3;
        uint32_t doff = (uint32_t)row * 64u + (uint32_t)((c ^ ((row >> 1) & 3)) << 4);
        CP16(stage + 8192u + doff, Wh + (size_t)(n0 + row) * DM + kt * 32 + c * 8);
    }
    CP_COMMIT();
}

__global__ __launch_bounds__(512) void proj_mma_kernel(
    const unsigned short* __restrict__ Xh,
    const unsigned short* __restrict__ Wh,
    const float* __restrict__ bias,
    float scale,
    unsigned short* __restrict__ dst)
{
    extern __shared__ char ps[];
    const uint32_t sb = smem_u32(ps);

    const int tid = threadIdx.x, lane = tid & 31, wid = tid >> 5;
    const int wm = wid & 3, wn = wid >> 2;
    const int m0 = blockIdx.y * 128, n0 = blockIdx.x * 256;
    const int flr = lane & 15, flc = lane >> 4;

    float C[2][8][4];
#pragma unroll
    for (int i = 0; i < 2; ++i)
#pragma unroll
        for (int j = 0; j < 8; ++j)
#pragma unroll
            for (int k = 0; k < 4; ++k) C[i][j][k] = 0.f;

    proj_issue(sb, 0, 0, tid, m0, n0, Xh, Wh);
    proj_issue(sb, 1, 1, tid, m0, n0, Xh, Wh);
    proj_issue(sb, 2, 2, tid, m0, n0, Xh, Wh);

    for (int kt = 0; kt < 32; ++kt) {
        if (kt < 30) CP_WAIT2(); else if (kt < 31) CP_WAIT1(); else CP_WAIT0();
        __syncthreads();
        if (kt + 3 < 32)
            proj_issue(sb, (kt + 3) & 3, kt + 3, tid, m0, n0, Xh, Wh);

        const uint32_t base = sb + (uint32_t)(kt & 3) * PSTG;
#pragma unroll
        for (int ks = 0; ks < 2; ++ks) {
            const uint32_t csw = (uint32_t)(((2 * ks + flc) ^ ((flr >> 1) & 3)) << 4);
            uint32_t a4[2][4];
#pragma unroll
            for (int mt = 0; mt < 2; ++mt) {
                uint32_t off = (uint32_t)((32 * wm + 16 * mt + flr) * 64) + csw;
                ldsm4(base + off, a4[mt]);
            }
#pragma unroll
            for (int ntp = 0; ntp < 4; ++ntp) {
                uint32_t boff = (uint32_t)((64 * wn + 16 * ntp + flr) * 64) + csw;
                uint32_t b4[4];
                ldsm4(base + 8192u + boff, b4);
                mma16816f(C[0][2 * ntp],     a4[0], b4[0], b4[2]);
                mma16816f(C[1][2 * ntp],     a4[1], b4[0], b4[2]);
                mma16816f(C[0][2 * ntp + 1], a4[0], b4[1], b4[3]);
                mma16816f(C[1][2 * ntp + 1], a4[1], b4[1], b4[3]);
            }
        }
    }

#pragma unroll
    for (int nt = 0; nt < 8; ++nt) {
        int n = n0 + 64 * wn + 8 * nt + 2 * (lane & 3);
        int h = n >> 6, d = n & 63;
        float2 bv = *(const float2*)(bias + n);
#pragma unroll
        for (int mt = 0; mt < 2; ++mt) {
            int mbase = m0 + 32 * wm + 16 * mt + (lane >> 2);
#pragma unroll
            for (int half = 0; half < 2; ++half) {
                int m = mbase + 8 * half;
                int b = m >> 11, s = m & (S_ - 1);
                float vx = (C[mt][nt][2 * half + 0] + bv.x) * scale;
                float vy = (C[mt][nt][2 * half + 1] + bv.y) * scale;
                size_t off = ((size_t)(b * H_ + h) * S_ + s) * DH + d;
                *(uint32_t*)(dst + off) = cvt2_f16(vx, vy);
            }
        }
    }
}

// ---------------------------------------------------------------------------
// Flash attention: fp16, 256 threads (8 warps x 16 q-rows = 128 q-rows/CTA),
// 2 CTAs/SM. 4-stage cp.async K/V + register-prefetched fragment-major mask.
// Stage (16KB): K@0 | V@8K, 4 stages. Q plane @65536 (16KB). Total 81920.
// ---------------------------------------------------------------------------
#define ASTG 16384u
#define AQOFF 65536u
#define ATTN_SMEM 81920u

__device__ __forceinline__ void attn_issue_kv(uint32_t sb, int st, int kt,
                                              int tid, size_t bhS) {
#pragma unroll
    for (int j = 0; j < 4; ++j) {
        int cid = tid + 256 * j;
        int sub = cid >> 9, w = cid & 511, row = w >> 3, c = w & 7;
        const unsigned short* plane = sub ? g_vh : g_kh;
        const void* src = plane + (bhS + (size_t)(kt * 64 + row)) * DH + c * 8;
        uint32_t dst = sb + (uint32_t)st * ASTG + (uint32_t)sub * 8192u
                     + (uint32_t)row * 128u + (uint32_t)((c ^ (row & 7)) << 4);
        CP16(dst, src);
    }
    CP_COMMIT();
}

__global__ __launch_bounds__(256, 2) void attn_mma_kernel(float* __restrict__ out)
{
    extern __shared__ char as_[];
    const uint32_t sb = smem_u32(as_);

    const int tid = threadIdx.x, lane = tid & 31, wid = tid >> 5;
    const int bz = blockIdx.z, h = blockIdx.y;
    const int qb = blockIdx.x;
    const int q0 = qb * 128;
    const size_t bhS = (size_t)(bz * H_ + h) * S_;

    const int flr = lane & 15, flc = lane >> 4;
    const int r_in = lane >> 2;
    const int c_in = 2 * (lane & 3);

    // prologue: Q plane (in group 0) + tiles 0,1,2
    {
#pragma unroll
        for (int j = 0; j < 4; ++j) {
            int cid = tid + 256 * j;
            int row = cid >> 3, c = cid & 7;
            const void* src = g_qh + (bhS + (size_t)(q0 + row)) * DH + c * 8;
            uint32_t dst = sb + AQOFF
                         + (uint32_t)row * 128u + (uint32_t)((c ^ (row & 7)) << 4);
            CP16(dst, src);
        }
    }
    attn_issue_kv(sb, 0, 0, tid, bhS);
    attn_issue_kv(sb, 1, 1, tid, bhS);
    attn_issue_kv(sb, 2, 2, tid, bhS);

    // fragment-major mask base; prefetch tile 0's bias
    const uint4* mb4 = (const uint4*)g_mb
                     + ((size_t)(bz * 16 + qb) * 32) * 4 * 256 + tid;
    uint4 mc0 = mb4[0];
    uint4 mc1 = mb4[256];
    uint4 mc2 = mb4[512];
    uint4 mc3 = mb4[768];

    // wait for group 0 (Q + tile0), hoist Q fragments
    CP_WAIT2();
    __syncthreads();
    const int qrow = 16 * wid + flr;
    uint32_t qf[4][4];
#pragma unroll
    for (int ks = 0; ks < 4; ++ks) {
        uint32_t qoff = (uint32_t)(qrow * 128)
                      + (uint32_t)(((2 * ks + flc) ^ (qrow & 7)) << 4);
        ldsm4(sb + AQOFF + qoff, qf[ks]);
    }

    float oC[8][4];
#pragma unroll
    for (int j = 0; j < 8; ++j)
#pragma unroll
        for (int k = 0; k < 4; ++k) oC[j][k] = 0.f;
    float mi0 = NEGINF, mi1 = NEGINF, li0 = 0.f, li1 = 0.f;

    const int rowA0 = q0 + 16 * wid + r_in;

    for (int kt = 0; kt < 32; ++kt) {
        if (kt < 30) CP_WAIT2(); else if (kt < 31) CP_WAIT1(); else CP_WAIT0();
        __syncthreads();
        if (kt + 3 < 32) attn_issue_kv(sb, (kt + 3) & 3, kt + 3, tid, bhS);

        const uint32_t base = sb + (uint32_t)(kt & 3) * ASTG;

        // S init from prefetched bias registers
        float sC[8][4];
        {
            uint32_t a0[4] = {mc0.x, mc0.y, mc0.z, mc0.w};
            uint32_t a1[4] = {mc1.x, mc1.y, mc1.z, mc1.w};
            uint32_t a2[4] = {mc2.x, mc2.y, mc2.z, mc2.w};
            uint32_t a3[4] = {mc3.x, mc3.y, mc3.z, mc3.w};
#pragma unroll
            for (int j = 0; j < 4; ++j) {
                sC[j][0]     = bf16lo_f(a0[j]); sC[j][1]     = bf16hi_f(a0[j]);
                sC[4 + j][0] = bf16lo_f(a1[j]); sC[4 + j][1] = bf16hi_f(a1[j]);
                sC[j][2]     = bf16lo_f(a2[j]); sC[j][3]     = bf16hi_f(a2[j]);
                sC[4 + j][2] = bf16lo_f(a3[j]); sC[4 + j][3] = bf16hi_f(a3[j]);
            }
        }
        // prefetch next tile's bias
        if (kt + 1 < 32) {
            const uint4* mn = mb4 + (size_t)(kt + 1) * 4 * 256;
            mc0 = mn[0];
            mc1 = mn[256];
            mc2 = mn[512];
            mc3 = mn[768];
        }

        // -- S += Q K^T --
#pragma unroll
        for (int ks = 0; ks < 4; ++ks) {
            uint32_t k4[4][4];
#pragma unroll
            for (int ntp = 0; ntp < 4; ++ntp) {
                uint32_t koff = (uint32_t)((16 * ntp + flr) * 128)
                              + (uint32_t)(((2 * ks + flc) ^ (flr & 7)) << 4);
                ldsm4(base + koff, k4[ntp]);
            }
#pragma unroll
            for (int ntp = 0; ntp < 4; ++ntp) {
                mma16816f(sC[2 * ntp],     qf[ks], k4[ntp][0], k4[ntp][2]);
                mma16816f(sC[2 * ntp + 1], qf[ks], k4[ntp][1], k4[ntp][3]);
            }
        }

        // -- online softmax (log2 domain) --
        float mx0 = NEGINF, mx1 = NEGINF;
#pragma unroll
        for (int nt = 0; nt < 8; ++nt) {
            mx0 = fmaxf(mx0, fmaxf(sC[nt][0], sC[nt][1]));
            mx1 = fmaxf(mx1, fmaxf(sC[nt][2], sC[nt][3]));
        }
        mx0 = fmaxf(mx0, __shfl_xor_sync(0xffffffffu, mx0, 1));
        mx0 = fmaxf(mx0, __shfl_xor_sync(0xffffffffu, mx0, 2));
        mx1 = fmaxf(mx1, __shfl_xor_sync(0xffffffffu, mx1, 1));
        mx1 = fmaxf(mx1, __shfl_xor_sync(0xffffffffu, mx1, 2));

        float mn0 = fmaxf(mi0, mx0), mn1 = fmaxf(mi1, mx1);
        float f0 = ex2f(mi0 - mn0), f1 = ex2f(mi1 - mn1);
        float sum0 = 0.f, sum1 = 0.f;
#pragma unroll
        for (int nt = 0; nt < 8; ++nt) {
            sC[nt][0] = ex2f(sC[nt][0] - mn0);
            sC[nt][1] = ex2f(sC[nt][1] - mn0);
            sC[nt][2] = ex2f(sC[nt][2] - mn1);
            sC[nt][3] = ex2f(sC[nt][3] - mn1);
            sum0 += sC[nt][0] + sC[nt][1];
            sum1 += sC[nt][2] + sC[nt][3];
        }
        sum0 += __shfl_xor_sync(0xffffffffu, sum0, 1);
        sum0 += __shfl_xor_sync(0xffffffffu, sum0, 2);
        sum1 += __shfl_xor_sync(0xffffffffu, sum1, 1);
        sum1 += __shfl_xor_sync(0xffffffffu, sum1, 2);
        li0 = li0 * f0 + sum0;
        li1 = li1 * f1 + sum1;
        mi0 = mn0; mi1 = mn1;
#pragma unroll
        for (int nt = 0; nt < 8; ++nt) {
            oC[nt][0] *= f0; oC[nt][1] *= f0;
            oC[nt][2] *= f1; oC[nt][3] *= f1;
        }

        // -- O += P V --
#pragma unroll
        for (int kp = 0; kp < 4; ++kp) {
            uint32_t pa[4];
            pa[0] = cvt2_f16(sC[2 * kp][0],     sC[2 * kp][1]);
            pa[1] = cvt2_f16(sC[2 * kp][2],     sC[2 * kp][3]);
            pa[2] = cvt2_f16(sC[2 * kp + 1][0], sC[2 * kp + 1][1]);
            pa[3] = cvt2_f16(sC[2 * kp + 1][2], sC[2 * kp + 1][3]);

            const int trow = kp * 16 + ((lane >> 3) & 1) * 8 + (lane & 7);
            const int cb = lane >> 4;
            uint32_t v4[4][4];
#pragma unroll
            for (int ntp = 0; ntp < 4; ++ntp) {
                uint32_t voff = (uint32_t)(trow * 128)
                              + (uint32_t)(((2 * ntp + cb) ^ (trow & 7)) << 4);
                ldsm4t(base + 8192u + voff, v4[ntp]);
            }
#pragma unroll
            for (int ntp = 0; ntp < 4; ++ntp) {
                mma16816f(oC[2 * ntp],     pa, v4[ntp][0], v4[ntp][1]);
                mma16816f(oC[2 * ntp + 1], pa, v4[ntp][2], v4[ntp][3]);
            }
        }
    }

    // ---- epilogue ----
    float inv0 = (li0 > 0.f) ? 1.0f / li0 : 0.f;
    float inv1 = (li1 > 0.f) ? 1.0f / li1 : 0.f;
    const int qr = rowA0;
    const int d0 = h * DH + c_in;
#pragma unroll
    for (int nt = 0; nt < 8; ++nt) {
        float2 v0, v1;
        v0.x = oC[nt][0] * inv0; v0.y = oC[nt][1] * inv0;
        v1.x = oC[nt][2] * inv1; v1.y = oC[nt][3] * inv1;
        *(float2*)(out + (size_t)(bz * S_ + qr) * DM + d0 + 8 * nt) = v0;
        *(float2*)(out + (size_t)(bz * S_ + qr + 8) * DM + d0 + 8 * nt) = v1;
    }
}

// ---------------------------------------------------------------------------
extern "C" void kernel_launch(void* const* d_in, const int* in_sizes, int n_in,
                              void* d_out, int out_size) {
    const void* mask = d_in[3];
    float* out = (float*)d_out;

    static int init_done = 0;
    static cudaStream_t s2 = 0, sA = 0, sB = 0;
    static cudaEvent_t ev0 = 0, evM = 0, evK = 0, evV = 0;
    static unsigned short *p_xh = 0, *p_wh = 0, *p_qh = 0, *p_kh = 0, *p_vh = 0;
    if (!init_done) {
        cudaFuncSetAttribute(proj_mma_kernel,
                             cudaFuncAttributeMaxDynamicSharedMemorySize, PROJ_SMEM);
        cudaFuncSetAttribute(attn_mma_kernel,
                             cudaFuncAttributeMaxDynamicSharedMemorySize, ATTN_SMEM);
        if (cudaStreamCreateWithFlags(&s2, cudaStreamNonBlocking) != cudaSuccess) s2 = 0;
        if (cudaStreamCreateWithFlags(&sA, cudaStreamNonBlocking) != cudaSuccess) sA = 0;
        if (cudaStreamCreateWithFlags(&sB, cudaStreamNonBlocking) != cudaSuccess) sB = 0;
        cudaEventCreateWithFlags(&ev0, cudaEventDisableTiming);
        cudaEventCreateWithFlags(&evM, cudaEventDisableTiming);
        cudaEventCreateWithFlags(&evK, cudaEventDisableTiming);
        cudaEventCreateWithFlags(&evV, cudaEventDisableTiming);
        cudaGetSymbolAddress((void**)&p_xh, g_xh);
        cudaGetSymbolAddress((void**)&p_wh, g_wh);
        cudaGetSymbolAddress((void**)&p_qh, g_qh);
        cudaGetSymbolAddress((void**)&p_kh, g_kh);
        cudaGetSymbolAddress((void**)&p_vh, g_vh);
        init_done = 1;
    }
    const bool multi = (s2 && sA && sB);

    dim3 cgrid(512, 1, 2);
    dim3 pgrid(4, 32, 1);

    const float* bq = (const float*)d_in[5];
    const float* bk = (const float*)d_in[7];
    const float* bv = (const float*)d_in[9];

    if (multi) {
        cudaEventRecord(ev0, 0);
        cudaStreamWaitEvent(s2, ev0, 0);
        cudaStreamWaitEvent(sA, ev0, 0);
        cudaStreamWaitEvent(sB, ev0, 0);

        // mask pipeline on s2
        detect_mask_kernel<<<1, 256, 0, s2>>>((const unsigned int*)mask);
        mask_conv_kernel<<<4096, 256, 0, s2>>>(mask);
        cudaEventRecord(evM, s2);

        // per-projection convert -> proj pipelines
        convert_pair_kernel<<<cgrid, 256>>>(
            (const float*)d_in[0], (const float*)d_in[4], 0);
        convert_pair_kernel<<<cgrid, 256, 0, sA>>>(
            (const float*)d_in[1], (const float*)d_in[6], 1);
        convert_pair_kernel<<<cgrid, 256, 0, sB>>>(
            (const float*)d_in[2], (const float*)d_in[8], 2);

        proj_mma_kernel<<<pgrid, 512, PROJ_SMEM>>>(
            p_xh, p_wh, bq, QSCALE, p_qh);
        proj_mma_kernel<<<pgrid, 512, PROJ_SMEM, sA>>>(
            p_xh + (size_t)XSEG, p_wh + (size_t)WSEG, bk, 1.0f, p_kh);
        proj_mma_kernel<<<pgrid, 512, PROJ_SMEM, sB>>>(
            p_xh + 2 * (size_t)XSEG, p_wh + 2 * (size_t)WSEG, bv, 1.0f, p_vh);
        cudaEventRecord(evK, sA);
        cudaEventRecord(evV, sB);

        cudaStreamWaitEvent(0, evM, 0);
        cudaStreamWaitEvent(0, evK, 0);
        cudaStreamWaitEvent(0, evV, 0);
    } else {
        detect_mask_kernel<<<1, 256>>>((const unsigned int*)mask);
        mask_conv_kernel<<<4096, 256>>>(mask);
        convert_pair_kernel<<<cgrid, 256>>>(
            (const float*)d_in[0], (const float*)d_in[4], 0);
        convert_pair_kernel<<<cgrid, 256>>>(
            (const float*)d_in[1], (const float*)d_in[6], 1);
        convert_pair_kernel<<<cgrid, 256>>>(
            (const float*)d_in[2], (const float*)d_in[8], 2);
        proj_mma_kernel<<<pgrid, 512, PROJ_SMEM>>>(
            p_xh, p_wh, bq, QSCALE, p_qh);
        proj_mma_kernel<<<pgrid, 512, PROJ_SMEM>>>(
            p_xh + (size_t)XSEG, p_wh + (size_t)WSEG, bk, 1.0f, p_kh);
        proj_mma_kernel<<<pgrid, 512, PROJ_SMEM>>>(
            p_xh + 2 * (size_t)XSEG, p_wh + 2 * (size_t)WSEG, bv, 1.0f, p_vh);
    }

    attn_mma_kernel<<<dim3(16, 16, 2), 256, ATTN_SMEM>>>(out);
}